// round 14
// baseline (speedup 1.0000x reference)
#include <cuda_runtime.h>
#include <math.h>
#include <stdint.h>

#define T_STEPS 128
#define BATCH   128
#define SAMP    8
#define DIN     64
#define RDIM    256
#define ZDIM    128
#define HDIM    512
#define BS      1024
#define TB      16384
#define NTHR    512

#define DT       0.05f
#define SQRT_DT  0.22360679774997896f
#define LOG_2PI  1.8378770664093453f

// ---------------- scratch ---------------------------------------------------
__device__ __align__(16) float g_Hh[TB * HDIM];
__device__ __align__(16) float g_Hhpos[TB * HDIM];
__device__ __align__(16) float g_Hph[TB * HDIM];
__device__ __align__(16) float g_Hf[TB * HDIM];
__device__ __align__(16) float g_diff[TB * ZDIM];
__device__ __align__(16) float g_Mt[T_STEPS * BATCH];
__device__ __align__(16) float g_z[BS * ZDIM];
// bf16 transposed weights: WT[n][k/2] packed pairs (k even lo, k odd hi)
__device__ __align__(16) unsigned g_Wd1zT[HDIM * ZDIM / 2];  // [512][64]
__device__ __align__(16) unsigned g_Wd2T[ZDIM * HDIM / 2];   // [128][256]
__device__ __align__(16) unsigned g_Wp1zT[HDIM * ZDIM / 2];  // [512][64]
__device__ __align__(16) unsigned g_Wp2T[ZDIM * HDIM / 2];   // [128][256]
__device__ float g_kldpart[T_STEPS * 64];
__device__ float g_reconpart[T_STEPS * 64];
__device__ int g_flag[64];
__device__ int g_ack[64];

__device__ __forceinline__ float4 ldcg4(const float* p) { return __ldcg((const float4*)p); }
__device__ __forceinline__ float2 ldcg2(const float* p) { return __ldcg((const float2*)p); }
__device__ __forceinline__ unsigned f2tf(float f) {
    unsigned r; asm("cvt.rna.tf32.f32 %0, %1;" : "=r"(r) : "f"(f)); return r;
}
__device__ __forceinline__ unsigned packbf(float lo, float hi) {
    unsigned r; asm("cvt.rn.bf16x2.f32 %0, %1, %2;" : "=r"(r) : "f"(hi), "f"(lo)); return r;
}
#define FU(x)  __float_as_uint(x)
#define UF(x)  __uint_as_float(x)

__device__ __forceinline__ void mma8(float c[4], const unsigned a[4],
                                     unsigned b0, unsigned b1)
{
    asm volatile(
        "mma.sync.aligned.m16n8k8.row.col.f32.tf32.tf32.f32 "
        "{%0,%1,%2,%3}, {%4,%5,%6,%7}, {%8,%9}, {%0,%1,%2,%3};"
        : "+f"(c[0]), "+f"(c[1]), "+f"(c[2]), "+f"(c[3])
        : "r"(a[0]), "r"(a[1]), "r"(a[2]), "r"(a[3]), "r"(b0), "r"(b1));
}
__device__ __forceinline__ void mma16(float c[4], const unsigned a[4],
                                      unsigned b0, unsigned b1)
{
    asm volatile(
        "mma.sync.aligned.m16n8k16.row.col.f32.bf16.bf16.f32 "
        "{%0,%1,%2,%3}, {%4,%5,%6,%7}, {%8,%9}, {%0,%1,%2,%3};"
        : "+f"(c[0]), "+f"(c[1]), "+f"(c[2]), "+f"(c[3])
        : "r"(a[0]), "r"(a[1]), "r"(a[2]), "r"(a[3]), "r"(b0), "r"(b1));
}

// cp.async helpers
__device__ __forceinline__ void cpasync16(unsigned dst, const void* src)
{
    asm volatile("cp.async.cg.shared.global [%0], [%1], 16;" :: "r"(dst), "l"(src));
}
#define CP_COMMIT() asm volatile("cp.async.commit_group;" ::: "memory")
#define CP_WAIT1()  asm volatile("cp.async.wait_group 1;" ::: "memory")

// ---------------- fused prep: z0 + Mt + 4 weight transposes ------------------
__global__ void prep_kernel(const float* __restrict__ cov,
                            const float* __restrict__ Wc1, const float* __restrict__ bc1,
                            const float* __restrict__ Wc2, const float* __restrict__ bc2,
                            const float* __restrict__ M,
                            const float* __restrict__ Wd1, const float* __restrict__ Wd2,
                            const float* __restrict__ Wp1, const float* __restrict__ Wp2)
{
    const int bid = blockIdx.x;
    const int tid = threadIdx.x;   // 256
    if (bid < 128) {
        __shared__ float sc[32];
        __shared__ float shh[64];
        int b = bid;
        if (tid < 32) sc[tid] = cov[b * 32 + tid];
        __syncthreads();
        if (tid < 64) {
            float acc = bc1[tid];
            #pragma unroll
            for (int c = 0; c < 32; c++) acc = fmaf(sc[c], Wc1[c * 64 + tid], acc);
            shh[tid] = fmaxf(acc, 0.f);
        }
        __syncthreads();
        if (tid < 128) {
            float acc = bc2[tid];
            #pragma unroll
            for (int k = 0; k < 64; k++) acc = fmaf(shh[k], Wc2[k * 128 + tid], acc);
            float z = tanhf(acc);
            #pragma unroll
            for (int s = 0; s < SAMP; s++)
                g_z[(b * SAMP + s) * ZDIM + tid] = z;
        }
    } else if (bid < 192) {
        int i = (bid - 128) * 256 + tid;
        const float4* p = (const float4*)(M + (size_t)i * DIN);
        float s = 0.f;
        #pragma unroll
        for (int j = 0; j < DIN / 4; j++) { float4 v = p[j]; s += v.x + v.y + v.z + v.w; }
        g_Mt[i] = s * (1.f / (float)DIN);
    } else {
        int r = bid - 192;
        int which = r >> 7;
        int local = r & 127;
        const float* W; unsigned* WT; int K, N, bx, by;
        if (which == 0)      { W = Wd1 + RDIM * HDIM; WT = g_Wd1zT; K = ZDIM; N = HDIM;
                               bx = local & 15, by = local >> 4; }
        else if (which == 1) { W = Wd2;               WT = g_Wd2T;  K = HDIM; N = ZDIM;
                               bx = local & 3,  by = local >> 2; }
        else if (which == 2) { W = Wp1 + RDIM * HDIM; WT = g_Wp1zT; K = ZDIM; N = HDIM;
                               bx = local & 15, by = local >> 4; }
        else                 { W = Wp2;               WT = g_Wp2T;  K = HDIM; N = ZDIM;
                               bx = local & 3,  by = local >> 2; }
        int n  = bx * 32 + (tid & 31);
        int kp = by * 8 + (tid >> 5);
        if (n < N && kp < K / 2) {
            float lo = W[(size_t)(2 * kp) * N + n];
            float hi = W[(size_t)(2 * kp + 1) * N + n];
            WT[(size_t)n * (K / 2) + kp] = packbf(lo, hi);
        }
    }
}

// ---------------- tf32 MMA precompute GEMM body -----------------------------
__device__ __forceinline__ void gemm_body(
    const float* __restrict__ A, const float* __restrict__ A2,
    const float* __restrict__ W, const float* __restrict__ bias,
    float* __restrict__ C, int M, int N, int K, int act,
    float* sA, float* sB)
{
    const int tid = threadIdx.x;
    const int w = tid >> 5, lane = tid & 31, g = lane >> 2, tig = lane & 3;
    const int bm = blockIdx.y * 64, bn = blockIdx.x * 128;
    const int mt = w & 3, n0 = (w >> 2) * 32;
    float acc[4][4] = {};
    for (int k0 = 0; k0 < K; k0 += 32) {
        __syncthreads();
        {
            int r = tid >> 3, c4 = (tid & 7) * 4;
            float4 av = *(const float4*)&A[(size_t)(bm + r) * K + k0 + c4];
            if (A2) {
                float4 b4 = *(const float4*)&A2[(size_t)(bm + r) * K + k0 + c4];
                av.x += b4.x; av.y += b4.y; av.z += b4.z; av.w += b4.w;
            }
            float* d = &sA[r * 36 + c4];
            d[0] = UF(f2tf(av.x)); d[1] = UF(f2tf(av.y));
            d[2] = UF(f2tf(av.z)); d[3] = UF(f2tf(av.w));
        }
        #pragma unroll
        for (int l = 0; l < 2; l++) {
            int v = tid + l * 512;
            int r = v >> 5, c4 = (v & 31) * 4;
            float4 wv = *(const float4*)&W[(size_t)(k0 + r) * N + bn + c4];
            float* d = &sB[r * 136 + c4];
            d[0] = UF(f2tf(wv.x)); d[1] = UF(f2tf(wv.y));
            d[2] = UF(f2tf(wv.z)); d[3] = UF(f2tf(wv.w));
        }
        __syncthreads();
        const float* pA = sA + (mt * 16 + g) * 36 + tig;
        const float* pB = sB + tig * 136 + n0 + g;
        #pragma unroll
        for (int kk = 0; kk < 4; kk++) {
            unsigned a[4] = { FU(pA[kk*8]), FU(pA[kk*8 + 288]),
                              FU(pA[kk*8 + 4]), FU(pA[kk*8 + 292]) };
            #pragma unroll
            for (int nt = 0; nt < 4; nt++) {
                unsigned b0 = FU(pB[kk*8*136 + nt*8]);
                unsigned b1 = FU(pB[(kk*8 + 4)*136 + nt*8]);
                mma8(acc[nt], a, b0, b1);
            }
        }
    }
    #pragma unroll
    for (int nt = 0; nt < 4; nt++) {
        int cb = bn + n0 + nt * 8 + 2 * tig;
        float b0 = bias[cb], b1 = bias[cb + 1];
        #pragma unroll
        for (int rh = 0; rh < 2; rh++) {
            int row = bm + mt * 16 + g + rh * 8;
            float v0 = acc[nt][rh*2] + b0, v1 = acc[nt][rh*2 + 1] + b1;
            if (act == 1) { v0 = fmaxf(v0, 0.f); v1 = fmaxf(v1, 0.f); }
            if (act == 2) { v0 = expf(v0); v1 = expf(v1); }
            *(float2*)&C[(size_t)row * N + cb] = make_float2(v0, v1);
        }
    }
}

__global__ void __launch_bounds__(512, 2)
gemm_pre4(const float* __restrict__ ph, const float* __restrict__ phpos,
          const float* __restrict__ Wd1, const float* __restrict__ bd1,
          const float* __restrict__ Wp1, const float* __restrict__ bp1,
          const float* __restrict__ Wf1, const float* __restrict__ bf1)
{
    __shared__ float sA[64 * 36];
    __shared__ float sB[32 * 136];
    const int which = blockIdx.z;
    const float* A2   = (which == 1) ? phpos : nullptr;
    const float* W    = (which <= 1) ? Wd1 : (which == 2 ? Wp1 : Wf1);
    const float* bias = (which <= 1) ? bd1 : (which == 2 ? bp1 : bf1);
    float* C = (which == 0) ? g_Hh : (which == 1 ? g_Hhpos : (which == 2 ? g_Hph : g_Hf));
    gemm_body(ph, A2, W, bias, C, TB, HDIM, RDIM, (which == 3) ? 1 : 0, sA, sB);
}

__global__ void __launch_bounds__(512, 2)
gemm_diff(const float* __restrict__ Wf2, const float* __restrict__ bf2)
{
    __shared__ float sA[64 * 36];
    __shared__ float sB[32 * 136];
    gemm_body(g_Hf, nullptr, Wf2, bf2, g_diff, TB, ZDIM, HDIM, 2, sA, sB);
}

// ================= bf16 pairwise scan (cp.async W1 stream) ==================
// Block 2g: drift. Block 2g+1: p-head/NLL. 16 rows per pair, 1 block/SM.

// smem offsets (float/uint units) in DYNAMIC shared memory
#define ZB    0        /* z bf16 packed [16][68]        */
#define SAP   1088     /* A_p bf16 [16][68]             */
#define SAQ   2176     /* A_q bf16 [16][68] / LVO fp32  */
#define BB3   3264     /* stream triple buf 3 x [128][36] */
#define W2R   17088    /* resident W2 bf16 [128][260]   */
#define RED   50368    /* [32]                          */
#define SH_TOT 50400
#define SMEM_BYTES (SH_TOT * 4)
#define LVO   SAQ

// issue one W1 stage (local stage ls in 0..7) into buffer bsel via cp.async
__device__ __forceinline__ void issue_stage(unsigned* shu, const unsigned* W1T,
                                            int ls, int bsel, int tid)
{
    unsigned* dbuf = shu + BB3 + bsel * 4608;
    const unsigned* src = W1T + (size_t)((ls >> 1) * 128) * 64 + (ls & 1) * 32;
    unsigned d0 = (unsigned)__cvta_generic_to_shared(
        &dbuf[(tid >> 3) * 36 + (tid & 7) * 4]);
    unsigned d1 = (unsigned)__cvta_generic_to_shared(
        &dbuf[((tid + 512) >> 3) * 36 + ((tid + 512) & 7) * 4]);
    cpasync16(d0, src + (size_t)(tid >> 3) * 64 + (tid & 7) * 4);
    cpasync16(d1, src + (size_t)((tid + 512) >> 3) * 64 + ((tid + 512) & 7) * 4);
}

// preload z fragments (8 k16-groups x 4 regs) from ZB
__device__ __forceinline__ void load_za(const unsigned* shu, int g, int tig,
                                        unsigned za[8][4])
{
    const unsigned* pz = shu + ZB + g * 68 + tig;
    #pragma unroll
    for (int kk = 0; kk < 8; kk++) {
        za[kk][0] = pz[kk*8];
        za[kk][1] = pz[kk*8 + 544];
        za[kk][2] = pz[kk*8 + 4];
        za[kk][3] = pz[kk*8 + 548];
    }
}

// load resident W2 [128][256] -> smem [128][260]
__device__ __forceinline__ void load_w2r(unsigned* shu, const unsigned* W2T, int tid)
{
    #pragma unroll
    for (int i = 0; i < 16; i++) {
        int v = tid + i * 512;
        int r = v >> 6, c4 = (v & 63) * 4;
        *(uint4*)&shu[W2R + r * 260 + c4] = *(const uint4*)&W2T[(size_t)r * 256 + c4];
    }
}

__device__ void drift_step(int t, const float* __restrict__ bd2,
                           const float* __restrict__ noise,
                           const unsigned* __restrict__ W1T,
                           float* sh, float zr[4], int gidx,
                           float* __restrict__ out)
{
    unsigned* shu = (unsigned*)sh;
    const int tid = threadIdx.x;
    const int w = tid >> 5, lane = tid & 31, g = lane >> 2, tig = lane & 3;
    const int r0 = gidx * 16;

    // ---- step-top prefetches ----
    const int c = w * 8 + 2 * tig;
    const int cword = w * 4 + tig;
    const int bi0 = (r0 + g) >> 3,     si0 = (r0 + g) & 7;
    const int bi1 = (r0 + g + 8) >> 3, si1 = (r0 + g + 8) & 7;
    const size_t hb0 = (size_t)(t * BATCH + bi0) * HDIM;
    const size_t hb1 = (size_t)(t * BATCH + bi1) * HDIM;
    float2 hA0 = ldcg2(&g_Hh[hb0 + c]);
    float2 hA1 = ldcg2(&g_Hh[hb1 + c]);
    float2 hB0 = ldcg2(&g_Hhpos[hb0 + c]);
    float2 hB1 = ldcg2(&g_Hhpos[hb1 + c]);
    float2 dva = ldcg2(&g_diff[((size_t)t * BATCH + bi0) * ZDIM + c]);
    float2 dvb = ldcg2(&g_diff[((size_t)t * BATCH + bi1) * ZDIM + c]);
    float2 eva = ldcg2(&noise[(((size_t)t * BATCH + bi0) * SAMP + si0) * ZDIM + c]);
    float2 evb = ldcg2(&noise[(((size_t)t * BATCH + bi1) * SAMP + si1) * ZDIM + c]);
    float2 bia = *(const float2*)&bd2[c];

    unsigned za[8][4];
    load_za(shu, g, tig, za);

    float accp[4] = {0.f,0.f,0.f,0.f}, accq[4] = {0.f,0.f,0.f,0.f};

    for (int np = 0; np < 4; np++) {
        float ahz[4] = {0.f,0.f,0.f,0.f};
        #pragma unroll
        for (int st = 0; st < 2; st++) {
            const int sg = t * 8 + np * 2 + st;   // global stage counter
            unsigned* buf = shu + BB3 + (sg % 3) * 4608;
            CP_WAIT1();
            __syncthreads();
            {   // issue stage sg+2 (continuous stream across steps)
                int sg2 = sg + 2;
                if (sg2 < T_STEPS * 8)
                    issue_stage(shu, W1T, sg2 & 7, sg2 % 3, tid);
                CP_COMMIT();
            }
            const unsigned* pB = buf + (w * 8 + g) * 36 + tig;
            #pragma unroll
            for (int kk = 0; kk < 4; kk++)
                mma16(ahz, za[st * 4 + kk], pB[kk*8], pB[kk*8 + 4]);
        }
        {   // intra-warp A construction
            shu[SAP + g * 68 + cword] =
                packbf(fmaxf(hA0.x + ahz[0], 0.f), fmaxf(hA0.y + ahz[1], 0.f));
            shu[SAP + (g + 8) * 68 + cword] =
                packbf(fmaxf(hA1.x + ahz[2], 0.f), fmaxf(hA1.y + ahz[3], 0.f));
            shu[SAQ + g * 68 + cword] =
                packbf(fmaxf(hB0.x + ahz[0], 0.f), fmaxf(hB0.y + ahz[1], 0.f));
            shu[SAQ + (g + 8) * 68 + cword] =
                packbf(fmaxf(hB1.x + ahz[2], 0.f), fmaxf(hB1.y + ahz[3], 0.f));
            if (np < 3) {
                int po = (np + 1) * 128 + c;
                hA0 = ldcg2(&g_Hh[hb0 + po]);
                hA1 = ldcg2(&g_Hh[hb1 + po]);
                hB0 = ldcg2(&g_Hhpos[hb0 + po]);
                hB1 = ldcg2(&g_Hhpos[hb1 + po]);
            }
        }
        __syncthreads();
        // drift dual MMA: resident W2R, NO syncs
        #pragma unroll
        for (int st2 = 0; st2 < 2; st2++) {
            const unsigned* pAp = shu + SAP + g * 68 + st2 * 32 + tig;
            const unsigned* pAq = shu + SAQ + g * 68 + st2 * 32 + tig;
            const unsigned* pB2 = shu + W2R + (w * 8 + g) * 260 + np * 64 + st2 * 32 + tig;
            #pragma unroll
            for (int kk = 0; kk < 4; kk++) {
                unsigned ap[4] = { pAp[kk*8], pAp[kk*8 + 544], pAp[kk*8 + 4], pAp[kk*8 + 548] };
                unsigned aq[4] = { pAq[kk*8], pAq[kk*8 + 544], pAq[kk*8 + 4], pAq[kk*8 + 548] };
                unsigned b0 = pB2[kk*8], b1 = pB2[kk*8 + 4];
                mma16(accp, ap, b0, b1);
                mma16(accq, aq, b0, b1);
            }
        }
    }

    // ---- epilogue ----
    if (tid == 0) {
        while (((volatile int*)g_ack)[gidx] < t) __nanosleep(64);
    }
    __syncthreads();
    float kl = 0.f;
    {
        float pr0 = 0.1f * tanhf(accp[0] + bia.x);
        float pr1 = 0.1f * tanhf(accp[1] + bia.y);
        float po0 = 0.1f * tanhf(accq[0] + bia.x);
        float po1 = 0.1f * tanhf(accq[1] + bia.y);
        zr[0] += DT * po0 + SQRT_DT * dva.x * eva.x;
        zr[1] += DT * po1 + SQRT_DT * dva.y * eva.y;
        __stcg((float2*)&g_z[(size_t)(r0 + g) * ZDIM + c], make_float2(zr[0], zr[1]));
        if (t == T_STEPS - 1)
            *(float2*)&out[(size_t)(r0 + g) * ZDIM + c] = make_float2(zr[0], zr[1]);
        shu[ZB + g * 68 + (c >> 1)] = packbf(zr[0], zr[1]);
        float e0 = (pr0 - po0) / dva.x;
        float e1 = (pr1 - po1) / dva.y;
        kl += e0 * e0 + e1 * e1;
    }
    {
        float pr0 = 0.1f * tanhf(accp[2] + bia.x);
        float pr1 = 0.1f * tanhf(accp[3] + bia.y);
        float po0 = 0.1f * tanhf(accq[2] + bia.x);
        float po1 = 0.1f * tanhf(accq[3] + bia.y);
        zr[2] += DT * po0 + SQRT_DT * dvb.x * evb.x;
        zr[3] += DT * po1 + SQRT_DT * dvb.y * evb.y;
        __stcg((float2*)&g_z[(size_t)(r0 + g + 8) * ZDIM + c], make_float2(zr[2], zr[3]));
        if (t == T_STEPS - 1)
            *(float2*)&out[(size_t)(r0 + g + 8) * ZDIM + c] = make_float2(zr[2], zr[3]);
        shu[ZB + (g + 8) * 68 + (c >> 1)] = packbf(zr[2], zr[3]);
        float e0 = (pr0 - po0) / dvb.x;
        float e1 = (pr1 - po1) / dvb.y;
        kl += e0 * e0 + e1 * e1;
    }
    __threadfence();
    __syncthreads();
    if (tid == 0) ((volatile int*)g_flag)[gidx] = t + 1;
    #pragma unroll
    for (int o = 16; o > 0; o >>= 1) kl += __shfl_xor_sync(~0u, kl, o);
    if (lane == 0) sh[RED + w] = kl;
    __syncthreads();
    if (tid < 32) {
        float v = (tid < 16) ? sh[RED + tid] : 0.f;
        #pragma unroll
        for (int o = 8; o > 0; o >>= 1) v += __shfl_xor_sync(~0u, v, o);
        if (tid == 0) g_kldpart[t * 64 + gidx] = v;
    }
}

__device__ void p_step(int t, const float* __restrict__ bp2,
                       const float* __restrict__ X,
                       const unsigned* __restrict__ W1T,
                       float* sh, int gidx)
{
    unsigned* shu = (unsigned*)sh;
    const int tid = threadIdx.x;
    const int w = tid >> 5, lane = tid & 31, g = lane >> 2, tig = lane & 3;
    const int r0 = gidx * 16;

    // ---- step-top prefetches (independent of the z flag) ----
    const int c = w * 8 + 2 * tig;
    const int cword = w * 4 + tig;
    const int bi0 = (r0 + g) >> 3, bi1 = (r0 + g + 8) >> 3;
    const size_t hb0 = (size_t)(t * BATCH + bi0) * HDIM;
    const size_t hb1 = (size_t)(t * BATCH + bi1) * HDIM;
    float2 hP0 = ldcg2(&g_Hph[hb0 + c]);
    float2 hP1 = ldcg2(&g_Hph[hb1 + c]);
    float mt0 = g_Mt[t * BATCH + bi0];
    float mt1 = g_Mt[t * BATCH + bi1];
    float2 xv0 = make_float2(0.f, 0.f), xv1 = make_float2(0.f, 0.f);
    float2 biam = make_float2(0.f, 0.f), bial = make_float2(0.f, 0.f);
    if (w < 8) {
        int mc = w * 8 + 2 * tig;
        xv0 = *(const float2*)&X[((size_t)t * BATCH + bi0) * DIN + mc];
        xv1 = *(const float2*)&X[((size_t)t * BATCH + bi1) * DIN + mc];
        biam = *(const float2*)&bp2[mc];
    } else {
        bial = *(const float2*)&bp2[64 + (w - 8) * 8 + 2 * tig];
    }

    // wait for z(t+1), stage to ZB bf16
    if (tid == 0) {
        while (((volatile int*)g_flag)[gidx] < t + 1) __nanosleep(64);
        __threadfence();
    }
    __syncthreads();
    {
        int r = tid >> 5, c4 = (tid & 31) * 4;
        float4 z4 = ldcg4(&g_z[(size_t)(r0 + r) * ZDIM + c4]);
        shu[ZB + r * 68 + (c4 >> 1)]     = packbf(z4.x, z4.y);
        shu[ZB + r * 68 + (c4 >> 1) + 1] = packbf(z4.z, z4.w);
    }
    __syncthreads();
    if (tid == 0) {
        __threadfence();
        ((volatile int*)g_ack)[gidx] = t + 1;
    }

    unsigned za[8][4];
    load_za(shu, g, tig, za);

    float acc[4] = {0.f,0.f,0.f,0.f};
    for (int np = 0; np < 4; np++) {
        float ahz[4] = {0.f,0.f,0.f,0.f};
        #pragma unroll
        for (int st = 0; st < 2; st++) {
            const int sg = t * 8 + np * 2 + st;
            unsigned* buf = shu + BB3 + (sg % 3) * 4608;
            CP_WAIT1();
            __syncthreads();
            {
                int sg2 = sg + 2;
                if (sg2 < T_STEPS * 8)
                    issue_stage(shu, W1T, sg2 & 7, sg2 % 3, tid);
                CP_COMMIT();
            }
            const unsigned* pB = buf + (w * 8 + g) * 36 + tig;
            #pragma unroll
            for (int kk = 0; kk < 4; kk++)
                mma16(ahz, za[st * 4 + kk], pB[kk*8], pB[kk*8 + 4]);
        }
        {   // intra-warp A construction
            shu[SAP + g * 68 + cword] =
                packbf(fmaxf(hP0.x + ahz[0], 0.f), fmaxf(hP0.y + ahz[1], 0.f));
            shu[SAP + (g + 8) * 68 + cword] =
                packbf(fmaxf(hP1.x + ahz[2], 0.f), fmaxf(hP1.y + ahz[3], 0.f));
            if (np < 3) {
                int po = (np + 1) * 128 + c;
                hP0 = ldcg2(&g_Hph[hb0 + po]);
                hP1 = ldcg2(&g_Hph[hb1 + po]);
            }
        }
        __syncthreads();
        #pragma unroll
        for (int st2 = 0; st2 < 2; st2++) {
            const unsigned* pAp = shu + SAP + g * 68 + st2 * 32 + tig;
            const unsigned* pB2 = shu + W2R + (w * 8 + g) * 260 + np * 64 + st2 * 32 + tig;
            #pragma unroll
            for (int kk = 0; kk < 4; kk++) {
                unsigned ap[4] = { pAp[kk*8], pAp[kk*8 + 544], pAp[kk*8 + 4], pAp[kk*8 + 548] };
                mma16(acc, ap, pB2[kk*8], pB2[kk*8 + 4]);
            }
        }
    }

    // ---- NLL epilogue ----
    __syncthreads();
    if (w >= 8) {
        int cb = (w - 8) * 8 + 2 * tig;
        *(float2*)&sh[LVO + g * 68 + cb]       = make_float2(acc[0] + bial.x, acc[1] + bial.y);
        *(float2*)&sh[LVO + (g + 8) * 68 + cb] = make_float2(acc[2] + bial.x, acc[3] + bial.y);
    }
    __syncthreads();
    float local = 0.f;
    if (w < 8) {
        int mc = w * 8 + 2 * tig;
        {
            float2 lv = *(float2*)&sh[LVO + g * 68 + mc];
            float m0 = acc[0] + biam.x, m1 = acc[1] + biam.y;
            float d0 = xv0.x - m0, d1 = xv0.y - m1;
            local += mt0 * 0.5f * (LOG_2PI + lv.x + d0 * d0 * expf(-lv.x));
            local += mt0 * 0.5f * (LOG_2PI + lv.y + d1 * d1 * expf(-lv.y));
        }
        {
            float2 lv = *(float2*)&sh[LVO + (g + 8) * 68 + mc];
            float m0 = acc[2] + biam.x, m1 = acc[3] + biam.y;
            float d0 = xv1.x - m0, d1 = xv1.y - m1;
            local += mt1 * 0.5f * (LOG_2PI + lv.x + d0 * d0 * expf(-lv.x));
            local += mt1 * 0.5f * (LOG_2PI + lv.y + d1 * d1 * expf(-lv.y));
        }
    }
    #pragma unroll
    for (int o = 16; o > 0; o >>= 1) local += __shfl_xor_sync(~0u, local, o);
    if (lane == 0) sh[RED + w] = local;
    __syncthreads();
    if (tid < 32) {
        float v = (tid < 16) ? sh[RED + tid] : 0.f;
        #pragma unroll
        for (int o = 8; o > 0; o >>= 1) v += __shfl_xor_sync(~0u, v, o);
        if (tid == 0) g_reconpart[t * 64 + gidx] = v;
    }
}

__global__ void __launch_bounds__(NTHR, 1)
scan_pairs(const float* __restrict__ bd2, const float* __restrict__ noise,
           const float* __restrict__ bp2, const float* __restrict__ X,
           float* __restrict__ out)
{
    extern __shared__ float sh[];
    unsigned* shu = (unsigned*)sh;
    const int role = blockIdx.x & 1;
    const int gidx = blockIdx.x >> 1;
    const int tid = threadIdx.x;
    const int w = tid >> 5, lane = tid & 31, g = lane >> 2, tig = lane & 3;
    const int r0 = gidx * 16;
    const unsigned* W1T = role ? g_Wp1zT : g_Wd1zT;

    // resident W2 (once per kernel)
    load_w2r(shu, role ? g_Wp2T : g_Wd2T, tid);

    // prime the W1 cp.async stream: stages 0 and 1
    issue_stage(shu, W1T, 0, 0, tid);
    CP_COMMIT();
    issue_stage(shu, W1T, 1, 1, tid);
    CP_COMMIT();

    if (role == 0) {
        {   // init ZB (bf16) from z0
            int r = tid >> 5, c4 = (tid & 31) * 4;
            float4 z4 = ldcg4(&g_z[(size_t)(r0 + r) * ZDIM + c4]);
            shu[ZB + r * 68 + (c4 >> 1)]     = packbf(z4.x, z4.y);
            shu[ZB + r * 68 + (c4 >> 1) + 1] = packbf(z4.z, z4.w);
        }
        float zr[4];
        {
            int c = w * 8 + 2 * tig;
            float2 a = ldcg2(&g_z[(size_t)(r0 + g) * ZDIM + c]);
            float2 b = ldcg2(&g_z[(size_t)(r0 + g + 8) * ZDIM + c]);
            zr[0] = a.x; zr[1] = a.y; zr[2] = b.x; zr[3] = b.y;
        }
        __syncthreads();
        for (int t = 0; t < T_STEPS; t++)
            drift_step(t, bd2, noise, W1T, sh, zr, gidx, out);
    } else {
        __syncthreads();
        for (int t = 0; t < T_STEPS; t++)
            p_step(t, bp2, X, W1T, sh, gidx);
    }
}

// ---------------- outputs ---------------------------------------------------
__global__ void finalize(float* __restrict__ out, int out_size)
{
    int tid = threadIdx.x;   // 256
    if (tid < 64) { g_flag[tid] = 0; g_ack[tid] = 0; }   // reset for graph replay
    float k = 0.f, r = 0.f;
    for (int i = tid; i < T_STEPS * 64; i += 256) k += g_kldpart[i];
    for (int i = tid; i < T_STEPS * 64; i += 256) r += g_reconpart[i];
    __shared__ float rk[256], rr[256];
    rk[tid] = k; rr[tid] = r;
    __syncthreads();
    for (int s = 128; s > 0; s >>= 1) {
        if (tid < s) { rk[tid] += rk[tid + s]; rr[tid] += rr[tid + s]; }
        __syncthreads();
    }
    if (tid == 0) {
        float kld   = rk[0] * (0.5f * DT / (float)BS);
        float recon = rr[0] * (1.f / (float)BS);
        out[out_size - 3] = recon + kld;
        out[out_size - 2] = recon;
        out[out_size - 1] = kld;
    }
}

// ---------------- launch ----------------------------------------------------
extern "C" void kernel_launch(void* const* d_in, const int* in_sizes, int n_in,
                              void* d_out, int out_size)
{
    const float* X     = (const float*)d_in[0];
    const float* M     = (const float*)d_in[1];
    const float* cov   = (const float*)d_in[2];
    const float* ph    = (const float*)d_in[3];
    const float* phpos = (const float*)d_in[4];
    const float* noise = (const float*)d_in[5];
    const float* Wc1 = (const float*)d_in[6],  *bc1 = (const float*)d_in[7];
    const float* Wc2 = (const float*)d_in[8],  *bc2 = (const float*)d_in[9];
    const float* Wd1 = (const float*)d_in[10], *bd1 = (const float*)d_in[11];
    const float* Wd2 = (const float*)d_in[12], *bd2 = (const float*)d_in[13];
    const float* Wf1 = (const float*)d_in[14], *bf1 = (const float*)d_in[15];
    const float* Wf2 = (const float*)d_in[16], *bf2 = (const float*)d_in[17];
    const float* Wp1 = (const float*)d_in[18], *bp1 = (const float*)d_in[19];
    const float* Wp2 = (const float*)d_in[20], *bp2 = (const float*)d_in[21];
    float* out = (float*)d_out;

    static int smem_set = 0;
    if (!smem_set) {
        cudaFuncSetAttribute(scan_pairs,
                             cudaFuncAttributeMaxDynamicSharedMemorySize, SMEM_BYTES);
        smem_set = 1;
    }

    // ---- fused prep: z0 + Mt + 4 weight transposes (one launch) ----
    prep_kernel<<<704, 256>>>(cov, Wc1, bc1, Wc2, bc2, M, Wd1, Wd2, Wp1, Wp2);
    // ---- big h-GEMMs (tf32 MMA) ----
    gemm_pre4<<<dim3(4, 256, 4), 512>>>(ph, phpos, Wd1, bd1, Wp1, bp1, Wf1, bf1);
    gemm_diff<<<dim3(1, 256), 512>>>(Wf2, bf2);

    // ---- bf16 pairwise scan (cp.async W1 stream) ----
    scan_pairs<<<128, NTHR, SMEM_BYTES>>>(bd2, noise, bp2, X, out);

    // ---- losses + flag reset ----
    finalize<<<1, 256>>>(out, out_size);
}

// round 15
// speedup vs baseline: 1.0470x; 1.0470x over previous
#include <cuda_runtime.h>
#include <math.h>
#include <stdint.h>

#define T_STEPS 128
#define BATCH   128
#define SAMP    8
#define DIN     64
#define RDIM    256
#define ZDIM    128
#define HDIM    512
#define BS      1024
#define TB      16384
#define NTHR    512

#define DT       0.05f
#define SQRT_DT  0.22360679774997896f
#define LOG_2PI  1.8378770664093453f

// ---------------- scratch ---------------------------------------------------
__device__ __align__(16) float g_Hh[TB * HDIM];
__device__ __align__(16) float g_Hhpos[TB * HDIM];
__device__ __align__(16) float g_Hph[TB * HDIM];
__device__ __align__(16) float g_Hf[TB * HDIM];
__device__ __align__(16) float g_diff[TB * ZDIM];
__device__ __align__(16) float g_Mt[T_STEPS * BATCH];
__device__ __align__(16) float g_z[BS * ZDIM];
// bf16 transposed weights: WT[n][k/2] packed pairs (k even lo, k odd hi)
__device__ __align__(16) unsigned g_Wd1zT[HDIM * ZDIM / 2];  // [512][64]
__device__ __align__(16) unsigned g_Wd2T[ZDIM * HDIM / 2];   // [128][256]
__device__ __align__(16) unsigned g_Wp1zT[HDIM * ZDIM / 2];  // [512][64]
__device__ __align__(16) unsigned g_Wp2T[ZDIM * HDIM / 2];   // [128][256]
__device__ float g_kldpart[T_STEPS * 64];
__device__ float g_reconpart[T_STEPS * 64];
__device__ int g_flag[64];
__device__ int g_ack[64];

__device__ __forceinline__ float4 ldcg4(const float* p) { return __ldcg((const float4*)p); }
__device__ __forceinline__ float2 ldcg2(const float* p) { return __ldcg((const float2*)p); }
__device__ __forceinline__ unsigned f2tf(float f) {
    unsigned r; asm("cvt.rna.tf32.f32 %0, %1;" : "=r"(r) : "f"(f)); return r;
}
__device__ __forceinline__ unsigned packbf(float lo, float hi) {
    unsigned r; asm("cvt.rn.bf16x2.f32 %0, %1, %2;" : "=r"(r) : "f"(hi), "f"(lo)); return r;
}
#define FU(x)  __float_as_uint(x)
#define UF(x)  __uint_as_float(x)

__device__ __forceinline__ void mma8(float c[4], const unsigned a[4],
                                     unsigned b0, unsigned b1)
{
    asm volatile(
        "mma.sync.aligned.m16n8k8.row.col.f32.tf32.tf32.f32 "
        "{%0,%1,%2,%3}, {%4,%5,%6,%7}, {%8,%9}, {%0,%1,%2,%3};"
        : "+f"(c[0]), "+f"(c[1]), "+f"(c[2]), "+f"(c[3])
        : "r"(a[0]), "r"(a[1]), "r"(a[2]), "r"(a[3]), "r"(b0), "r"(b1));
}
__device__ __forceinline__ void mma16(float c[4], const unsigned a[4],
                                      unsigned b0, unsigned b1)
{
    asm volatile(
        "mma.sync.aligned.m16n8k16.row.col.f32.bf16.bf16.f32 "
        "{%0,%1,%2,%3}, {%4,%5,%6,%7}, {%8,%9}, {%0,%1,%2,%3};"
        : "+f"(c[0]), "+f"(c[1]), "+f"(c[2]), "+f"(c[3])
        : "r"(a[0]), "r"(a[1]), "r"(a[2]), "r"(a[3]), "r"(b0), "r"(b1));
}

// ---------------- tf32 MMA precompute GEMM body -----------------------------
__device__ __forceinline__ void gemm_body(
    const float* __restrict__ A, const float* __restrict__ A2,
    const float* __restrict__ W, const float* __restrict__ bias,
    float* __restrict__ C, int M, int N, int K, int act,
    float* sA, float* sB)
{
    const int tid = threadIdx.x;
    const int w = tid >> 5, lane = tid & 31, g = lane >> 2, tig = lane & 3;
    const int bm = blockIdx.y * 64, bn = blockIdx.x * 128;
    const int mt = w & 3, n0 = (w >> 2) * 32;
    float acc[4][4] = {};
    for (int k0 = 0; k0 < K; k0 += 32) {
        __syncthreads();
        {
            int r = tid >> 3, c4 = (tid & 7) * 4;
            float4 av = *(const float4*)&A[(size_t)(bm + r) * K + k0 + c4];
            if (A2) {
                float4 b4 = *(const float4*)&A2[(size_t)(bm + r) * K + k0 + c4];
                av.x += b4.x; av.y += b4.y; av.z += b4.z; av.w += b4.w;
            }
            float* d = &sA[r * 36 + c4];
            d[0] = UF(f2tf(av.x)); d[1] = UF(f2tf(av.y));
            d[2] = UF(f2tf(av.z)); d[3] = UF(f2tf(av.w));
        }
        #pragma unroll
        for (int l = 0; l < 2; l++) {
            int v = tid + l * 512;
            int r = v >> 5, c4 = (v & 31) * 4;
            float4 wv = *(const float4*)&W[(size_t)(k0 + r) * N + bn + c4];
            float* d = &sB[r * 136 + c4];
            d[0] = UF(f2tf(wv.x)); d[1] = UF(f2tf(wv.y));
            d[2] = UF(f2tf(wv.z)); d[3] = UF(f2tf(wv.w));
        }
        __syncthreads();
        const float* pA = sA + (mt * 16 + g) * 36 + tig;
        const float* pB = sB + tig * 136 + n0 + g;
        #pragma unroll
        for (int kk = 0; kk < 4; kk++) {
            unsigned a[4] = { FU(pA[kk*8]), FU(pA[kk*8 + 288]),
                              FU(pA[kk*8 + 4]), FU(pA[kk*8 + 292]) };
            #pragma unroll
            for (int nt = 0; nt < 4; nt++) {
                unsigned b0 = FU(pB[kk*8*136 + nt*8]);
                unsigned b1 = FU(pB[(kk*8 + 4)*136 + nt*8]);
                mma8(acc[nt], a, b0, b1);
            }
        }
    }
    #pragma unroll
    for (int nt = 0; nt < 4; nt++) {
        int cb = bn + n0 + nt * 8 + 2 * tig;
        float b0 = bias[cb], b1 = bias[cb + 1];
        #pragma unroll
        for (int rh = 0; rh < 2; rh++) {
            int row = bm + mt * 16 + g + rh * 8;
            float v0 = acc[nt][rh*2] + b0, v1 = acc[nt][rh*2 + 1] + b1;
            if (act == 1) { v0 = fmaxf(v0, 0.f); v1 = fmaxf(v1, 0.f); }
            if (act == 2) { v0 = expf(v0); v1 = expf(v1); }
            *(float2*)&C[(size_t)row * N + cb] = make_float2(v0, v1);
        }
    }
}

// ---------------- prep body (z0 + Mt + transposes), pid in [0,704) ----------
__device__ void prep_body(int pid,
                          const float* __restrict__ cov,
                          const float* __restrict__ Wc1, const float* __restrict__ bc1,
                          const float* __restrict__ Wc2, const float* __restrict__ bc2,
                          const float* __restrict__ M,
                          const float* __restrict__ Wd1, const float* __restrict__ Wd2,
                          const float* __restrict__ Wp1, const float* __restrict__ Wp2,
                          float* sh)
{
    const int tid = threadIdx.x;   // 512, only tid<256 active for most
    if (pid < 128) {
        float* sc  = sh;        // [32]
        float* shh = sh + 32;   // [64]
        int b = pid;
        if (tid < 32) sc[tid] = cov[b * 32 + tid];
        __syncthreads();
        if (tid < 64) {
            float acc = bc1[tid];
            #pragma unroll
            for (int c = 0; c < 32; c++) acc = fmaf(sc[c], Wc1[c * 64 + tid], acc);
            shh[tid] = fmaxf(acc, 0.f);
        }
        __syncthreads();
        if (tid < 128) {
            float acc = bc2[tid];
            #pragma unroll
            for (int k = 0; k < 64; k++) acc = fmaf(shh[k], Wc2[k * 128 + tid], acc);
            float z = tanhf(acc);
            #pragma unroll
            for (int s = 0; s < SAMP; s++)
                g_z[(b * SAMP + s) * ZDIM + tid] = z;
        }
    } else if (pid < 160) {
        // Mt: 512 threads per block, 32 blocks cover 16384 rows
        int i = (pid - 128) * 512 + tid;
        const float4* p = (const float4*)(M + (size_t)i * DIN);
        float s = 0.f;
        #pragma unroll
        for (int j = 0; j < DIN / 4; j++) { float4 v = p[j]; s += v.x + v.y + v.z + v.w; }
        g_Mt[i] = s * (1.f / (float)DIN);
    } else if (pid < 672) {
        // transposes: 512 regions of 256 threads -> use 256 blocks of 512
        int r = pid - 160;          // 0..511
        int which = r >> 7;
        int local = r & 127;
        const float* W; unsigned* WT; int K, N, bx, by;
        if (which == 0)      { W = Wd1 + RDIM * HDIM; WT = g_Wd1zT; K = ZDIM; N = HDIM;
                               bx = local & 15, by = local >> 4; }
        else if (which == 1) { W = Wd2;               WT = g_Wd2T;  K = HDIM; N = ZDIM;
                               bx = local & 3,  by = local >> 2; }
        else if (which == 2) { W = Wp1 + RDIM * HDIM; WT = g_Wp1zT; K = ZDIM; N = HDIM;
                               bx = local & 15, by = local >> 4; }
        else                 { W = Wp2;               WT = g_Wp2T;  K = HDIM; N = ZDIM;
                               bx = local & 3,  by = local >> 2; }
        if (tid < 256) {
            int n  = bx * 32 + (tid & 31);
            int kp = by * 8 + (tid >> 5);
            if (n < N && kp < K / 2) {
                float lo = W[(size_t)(2 * kp) * N + n];
                float hi = W[(size_t)(2 * kp + 1) * N + n];
                WT[(size_t)n * (K / 2) + kp] = packbf(lo, hi);
            }
        }
    }
    // pid >= 672: idle filler blocks
}

// Fused 5-way: 4 h-projection GEMMs + prep (blockIdx.z == 4)
__global__ void __launch_bounds__(512, 2)
gemm_pre5(const float* __restrict__ ph, const float* __restrict__ phpos,
          const float* __restrict__ Wd1, const float* __restrict__ bd1,
          const float* __restrict__ Wp1, const float* __restrict__ bp1,
          const float* __restrict__ Wf1, const float* __restrict__ bf1,
          const float* __restrict__ cov,
          const float* __restrict__ Wc1, const float* __restrict__ bc1,
          const float* __restrict__ Wc2, const float* __restrict__ bc2,
          const float* __restrict__ M,
          const float* __restrict__ Wd2, const float* __restrict__ Wp2)
{
    __shared__ float sA[64 * 36];
    __shared__ float sB[32 * 136];
    const int which = blockIdx.z;
    if (which == 4) {
        int pid = blockIdx.y * 4 + blockIdx.x;   // 0..1023
        prep_body(pid, cov, Wc1, bc1, Wc2, bc2, M, Wd1, Wd2, Wp1, Wp2, sA);
        return;
    }
    const float* A2   = (which == 1) ? phpos : nullptr;
    const float* W    = (which <= 1) ? Wd1 : (which == 2 ? Wp1 : Wf1);
    const float* bias = (which <= 1) ? bd1 : (which == 2 ? bp1 : bf1);
    float* C = (which == 0) ? g_Hh : (which == 1 ? g_Hhpos : (which == 2 ? g_Hph : g_Hf));
    gemm_body(ph, A2, W, bias, C, TB, HDIM, RDIM, (which == 3) ? 1 : 0, sA, sB);
}

__global__ void __launch_bounds__(512, 2)
gemm_diff(const float* __restrict__ Wf2, const float* __restrict__ bf2)
{
    __shared__ float sA[64 * 36];
    __shared__ float sB[32 * 136];
    gemm_body(g_Hf, nullptr, Wf2, bf2, g_diff, TB, ZDIM, HDIM, 2, sA, sB);
}

// ================= bf16 pairwise scan (R13 core: streamed W1, resident W2) ==
// Block 2g: drift. Block 2g+1: p-head/NLL. 16 rows per pair, 1 block/SM.

// smem offsets (float/uint units) in DYNAMIC shared memory
#define ZB    0        /* z bf16 packed [16][68]        */
#define SAP   1088     /* A_p bf16 [16][68]             */
#define SAQ   2176     /* A_q bf16 [16][68] / LVO fp32  */
#define BB2   3264     /* stream dbl buf 2 x [128][36]  */
#define W2R   12480    /* resident W2 bf16 [128][260]   */
#define RED   45760    /* [32]                          */
#define SH_TOT 45792
#define SMEM_BYTES (SH_TOT * 4)
#define LVO   SAQ

__device__ __forceinline__ void pf_ld(const unsigned* base, int tid,
                                      uint4& b0, uint4& b1)
{
    b0 = *(const uint4*)(base + (size_t)(tid >> 3) * 64 + (tid & 7) * 4);
    b1 = *(const uint4*)(base + (size_t)((tid + 512) >> 3) * 64 + ((tid + 512) & 7) * 4);
}
__device__ __forceinline__ void pf_st(unsigned* buf, int tid, uint4 b0, uint4 b1)
{
    *(uint4*)&buf[(tid >> 3) * 36 + (tid & 7) * 4] = b0;
    *(uint4*)&buf[((tid + 512) >> 3) * 36 + ((tid + 512) & 7) * 4] = b1;
}

// preload z fragments (8 k16-groups x 4 regs) from ZB
__device__ __forceinline__ void load_za(const unsigned* shu, int g, int tig,
                                        unsigned za[8][4])
{
    const unsigned* pz = shu + ZB + g * 68 + tig;
    #pragma unroll
    for (int kk = 0; kk < 8; kk++) {
        za[kk][0] = pz[kk*8];
        za[kk][1] = pz[kk*8 + 544];
        za[kk][2] = pz[kk*8 + 4];
        za[kk][3] = pz[kk*8 + 548];
    }
}

// load resident W2 [128][256] -> smem [128][260]
__device__ __forceinline__ void load_w2r(unsigned* shu, const unsigned* W2T, int tid)
{
    #pragma unroll
    for (int i = 0; i < 16; i++) {
        int v = tid + i * 512;
        int r = v >> 6, c4 = (v & 63) * 4;
        *(uint4*)&shu[W2R + r * 260 + c4] = *(const uint4*)&W2T[(size_t)r * 256 + c4];
    }
}

__device__ void drift_step(int t, const float* __restrict__ bd2,
                           const float* __restrict__ noise,
                           float* sh, float zr[4], int gidx,
                           float* __restrict__ out)
{
    unsigned* shu = (unsigned*)sh;
    const int tid = threadIdx.x;
    const int w = tid >> 5, lane = tid & 31, g = lane >> 2, tig = lane & 3;
    const int r0 = gidx * 16;

    // ---- step-top prefetches (all in flight before any compute) ----
    uint4 br0, br1;
    pf_ld(g_Wd1zT, tid, br0, br1);                 // weight stage 0
    const int c = w * 8 + 2 * tig;
    const int cword = w * 4 + tig;
    const int bi0 = (r0 + g) >> 3,     si0 = (r0 + g) & 7;
    const int bi1 = (r0 + g + 8) >> 3, si1 = (r0 + g + 8) & 7;
    const size_t hb0 = (size_t)(t * BATCH + bi0) * HDIM;
    const size_t hb1 = (size_t)(t * BATCH + bi1) * HDIM;
    float2 hA0 = ldcg2(&g_Hh[hb0 + c]);
    float2 hA1 = ldcg2(&g_Hh[hb1 + c]);
    float2 hB0 = ldcg2(&g_Hhpos[hb0 + c]);
    float2 hB1 = ldcg2(&g_Hhpos[hb1 + c]);
    float2 dva = ldcg2(&g_diff[((size_t)t * BATCH + bi0) * ZDIM + c]);
    float2 dvb = ldcg2(&g_diff[((size_t)t * BATCH + bi1) * ZDIM + c]);
    float2 eva = ldcg2(&noise[(((size_t)t * BATCH + bi0) * SAMP + si0) * ZDIM + c]);
    float2 evb = ldcg2(&noise[(((size_t)t * BATCH + bi1) * SAMP + si1) * ZDIM + c]);
    float2 bia = *(const float2*)&bd2[c];

    unsigned za[8][4];
    load_za(shu, g, tig, za);

    float accp[4] = {0.f,0.f,0.f,0.f}, accq[4] = {0.f,0.f,0.f,0.f};

    for (int np = 0; np < 4; np++) {
        float ahz[4] = {0.f,0.f,0.f,0.f};
        #pragma unroll
        for (int st = 0; st < 2; st++) {
            int ss = np * 2 + st;
            unsigned* buf = shu + BB2 + (ss & 1) * 4608;
            pf_st(buf, tid, br0, br1);
            __syncthreads();
            if (ss < 7) {
                const unsigned* s = g_Wd1zT + (size_t)((ss + 1) >> 1) * 128 * 64
                                            + ((ss + 1) & 1) * 32;
                pf_ld(s, tid, br0, br1);
            }
            const unsigned* pB = buf + (w * 8 + g) * 36 + tig;
            #pragma unroll
            for (int kk = 0; kk < 4; kk++)
                mma16(ahz, za[st * 4 + kk], pB[kk*8], pB[kk*8 + 4]);
        }
        {   // intra-warp A construction: ahz fragment + h fragments -> SAP/SAQ
            shu[SAP + g * 68 + cword] =
                packbf(fmaxf(hA0.x + ahz[0], 0.f), fmaxf(hA0.y + ahz[1], 0.f));
            shu[SAP + (g + 8) * 68 + cword] =
                packbf(fmaxf(hA1.x + ahz[2], 0.f), fmaxf(hA1.y + ahz[3], 0.f));
            shu[SAQ + g * 68 + cword] =
                packbf(fmaxf(hB0.x + ahz[0], 0.f), fmaxf(hB0.y + ahz[1], 0.f));
            shu[SAQ + (g + 8) * 68 + cword] =
                packbf(fmaxf(hB1.x + ahz[2], 0.f), fmaxf(hB1.y + ahz[3], 0.f));
            if (np < 3) {   // prefetch next np h fragments
                int po = (np + 1) * 128 + c;
                hA0 = ldcg2(&g_Hh[hb0 + po]);
                hA1 = ldcg2(&g_Hh[hb1 + po]);
                hB0 = ldcg2(&g_Hhpos[hb0 + po]);
                hB1 = ldcg2(&g_Hhpos[hb1 + po]);
            }
        }
        __syncthreads();
        // drift dual MMA: resident W2R, NO syncs
        #pragma unroll
        for (int st2 = 0; st2 < 2; st2++) {
            const unsigned* pAp = shu + SAP + g * 68 + st2 * 32 + tig;
            const unsigned* pAq = shu + SAQ + g * 68 + st2 * 32 + tig;
            const unsigned* pB2 = shu + W2R + (w * 8 + g) * 260 + np * 64 + st2 * 32 + tig;
            #pragma unroll
            for (int kk = 0; kk < 4; kk++) {
                unsigned ap[4] = { pAp[kk*8], pAp[kk*8 + 544], pAp[kk*8 + 4], pAp[kk*8 + 548] };
                unsigned aq[4] = { pAq[kk*8], pAq[kk*8 + 544], pAq[kk*8 + 4], pAq[kk*8 + 548] };
                unsigned b0 = pB2[kk*8], b1 = pB2[kk*8 + 4];
                mma16(accp, ap, b0, b1);
                mma16(accq, aq, b0, b1);
            }
        }
    }

    // ---- epilogue: prior/poster, z update, KLD (operands prefetched) ----
    if (tid == 0) {
        while (((volatile int*)g_ack)[gidx] < t) __nanosleep(64);
    }
    __syncthreads();
    float kl = 0.f;
    {
        float pr0 = 0.1f * tanhf(accp[0] + bia.x);
        float pr1 = 0.1f * tanhf(accp[1] + bia.y);
        float po0 = 0.1f * tanhf(accq[0] + bia.x);
        float po1 = 0.1f * tanhf(accq[1] + bia.y);
        zr[0] += DT * po0 + SQRT_DT * dva.x * eva.x;
        zr[1] += DT * po1 + SQRT_DT * dva.y * eva.y;
        __stcg((float2*)&g_z[(size_t)(r0 + g) * ZDIM + c], make_float2(zr[0], zr[1]));
        if (t == T_STEPS - 1)
            *(float2*)&out[(size_t)(r0 + g) * ZDIM + c] = make_float2(zr[0], zr[1]);
        shu[ZB + g * 68 + (c >> 1)] = packbf(zr[0], zr[1]);
        float e0 = (pr0 - po0) / dva.x;
        float e1 = (pr1 - po1) / dva.y;
        kl += e0 * e0 + e1 * e1;
    }
    {
        float pr0 = 0.1f * tanhf(accp[2] + bia.x);
        float pr1 = 0.1f * tanhf(accp[3] + bia.y);
        float po0 = 0.1f * tanhf(accq[2] + bia.x);
        float po1 = 0.1f * tanhf(accq[3] + bia.y);
        zr[2] += DT * po0 + SQRT_DT * dvb.x * evb.x;
        zr[3] += DT * po1 + SQRT_DT * dvb.y * evb.y;
        __stcg((float2*)&g_z[(size_t)(r0 + g + 8) * ZDIM + c], make_float2(zr[2], zr[3]));
        if (t == T_STEPS - 1)
            *(float2*)&out[(size_t)(r0 + g + 8) * ZDIM + c] = make_float2(zr[2], zr[3]);
        shu[ZB + (g + 8) * 68 + (c >> 1)] = packbf(zr[2], zr[3]);
        float e0 = (pr0 - po0) / dvb.x;
        float e1 = (pr1 - po1) / dvb.y;
        kl += e0 * e0 + e1 * e1;
    }
    __threadfence();
    __syncthreads();
    if (tid == 0) ((volatile int*)g_flag)[gidx] = t + 1;
    #pragma unroll
    for (int o = 16; o > 0; o >>= 1) kl += __shfl_xor_sync(~0u, kl, o);
    if (lane == 0) sh[RED + w] = kl;
    __syncthreads();
    if (tid < 32) {
        float v = (tid < 16) ? sh[RED + tid] : 0.f;
        #pragma unroll
        for (int o = 8; o > 0; o >>= 1) v += __shfl_xor_sync(~0u, v, o);
        if (tid == 0) g_kldpart[t * 64 + gidx] = v;
    }
}

__device__ void p_step(int t, const float* __restrict__ bp2,
                       const float* __restrict__ X, float* sh, int gidx)
{
    unsigned* shu = (unsigned*)sh;
    const int tid = threadIdx.x;
    const int w = tid >> 5, lane = tid & 31, g = lane >> 2, tig = lane & 3;
    const int r0 = gidx * 16;

    // ---- step-top prefetches (independent of the z flag) ----
    uint4 br0, br1;
    pf_ld(g_Wp1zT, tid, br0, br1);
    const int c = w * 8 + 2 * tig;
    const int cword = w * 4 + tig;
    const int bi0 = (r0 + g) >> 3, bi1 = (r0 + g + 8) >> 3;
    const size_t hb0 = (size_t)(t * BATCH + bi0) * HDIM;
    const size_t hb1 = (size_t)(t * BATCH + bi1) * HDIM;
    float2 hP0 = ldcg2(&g_Hph[hb0 + c]);
    float2 hP1 = ldcg2(&g_Hph[hb1 + c]);
    float mt0 = g_Mt[t * BATCH + bi0];
    float mt1 = g_Mt[t * BATCH + bi1];
    float2 xv0 = make_float2(0.f, 0.f), xv1 = make_float2(0.f, 0.f);
    float2 biam = make_float2(0.f, 0.f), bial = make_float2(0.f, 0.f);
    if (w < 8) {
        int mc = w * 8 + 2 * tig;
        xv0 = *(const float2*)&X[((size_t)t * BATCH + bi0) * DIN + mc];
        xv1 = *(const float2*)&X[((size_t)t * BATCH + bi1) * DIN + mc];
        biam = *(const float2*)&bp2[mc];
    } else {
        bial = *(const float2*)&bp2[64 + (w - 8) * 8 + 2 * tig];
    }

    // wait for z(t+1), stage to ZB bf16
    if (tid == 0) {
        while (((volatile int*)g_flag)[gidx] < t + 1) __nanosleep(64);
        __threadfence();
    }
    __syncthreads();
    {
        int r = tid >> 5, c4 = (tid & 31) * 4;
        float4 z4 = ldcg4(&g_z[(size_t)(r0 + r) * ZDIM + c4]);
        shu[ZB + r * 68 + (c4 >> 1)]     = packbf(z4.x, z4.y);
        shu[ZB + r * 68 + (c4 >> 1) + 1] = packbf(z4.z, z4.w);
    }
    __syncthreads();
    if (tid == 0) {
        __threadfence();
        ((volatile int*)g_ack)[gidx] = t + 1;
    }

    unsigned za[8][4];
    load_za(shu, g, tig, za);

    float acc[4] = {0.f,0.f,0.f,0.f};
    for (int np = 0; np < 4; np++) {
        float ahz[4] = {0.f,0.f,0.f,0.f};
        #pragma unroll
        for (int st = 0; st < 2; st++) {
            int ss = np * 2 + st;
            unsigned* buf = shu + BB2 + (ss & 1) * 4608;
            pf_st(buf, tid, br0, br1);
            __syncthreads();
            if (ss < 7) {
                const unsigned* s = g_Wp1zT + (size_t)((ss + 1) >> 1) * 128 * 64
                                            + ((ss + 1) & 1) * 32;
                pf_ld(s, tid, br0, br1);
            }
            const unsigned* pB = buf + (w * 8 + g) * 36 + tig;
            #pragma unroll
            for (int kk = 0; kk < 4; kk++)
                mma16(ahz, za[st * 4 + kk], pB[kk*8], pB[kk*8 + 4]);
        }
        {   // intra-warp A construction
            shu[SAP + g * 68 + cword] =
                packbf(fmaxf(hP0.x + ahz[0], 0.f), fmaxf(hP0.y + ahz[1], 0.f));
            shu[SAP + (g + 8) * 68 + cword] =
                packbf(fmaxf(hP1.x + ahz[2], 0.f), fmaxf(hP1.y + ahz[3], 0.f));
            if (np < 3) {
                int po = (np + 1) * 128 + c;
                hP0 = ldcg2(&g_Hph[hb0 + po]);
                hP1 = ldcg2(&g_Hph[hb1 + po]);
            }
        }
        __syncthreads();
        #pragma unroll
        for (int st2 = 0; st2 < 2; st2++) {
            const unsigned* pAp = shu + SAP + g * 68 + st2 * 32 + tig;
            const unsigned* pB2 = shu + W2R + (w * 8 + g) * 260 + np * 64 + st2 * 32 + tig;
            #pragma unroll
            for (int kk = 0; kk < 4; kk++) {
                unsigned ap[4] = { pAp[kk*8], pAp[kk*8 + 544], pAp[kk*8 + 4], pAp[kk*8 + 548] };
                mma16(acc, ap, pB2[kk*8], pB2[kk*8 + 4]);
            }
        }
    }

    // ---- NLL epilogue (operands prefetched) ----
    __syncthreads();
    if (w >= 8) {   // logvar warps: export acc+bias (cols 64..127)
        int cb = (w - 8) * 8 + 2 * tig;
        *(float2*)&sh[LVO + g * 68 + cb]       = make_float2(acc[0] + bial.x, acc[1] + bial.y);
        *(float2*)&sh[LVO + (g + 8) * 68 + cb] = make_float2(acc[2] + bial.x, acc[3] + bial.y);
    }
    __syncthreads();
    float local = 0.f;
    if (w < 8) {
        int mc = w * 8 + 2 * tig;
        {
            float2 lv = *(float2*)&sh[LVO + g * 68 + mc];
            float m0 = acc[0] + biam.x, m1 = acc[1] + biam.y;
            float d0 = xv0.x - m0, d1 = xv0.y - m1;
            local += mt0 * 0.5f * (LOG_2PI + lv.x + d0 * d0 * expf(-lv.x));
            local += mt0 * 0.5f * (LOG_2PI + lv.y + d1 * d1 * expf(-lv.y));
        }
        {
            float2 lv = *(float2*)&sh[LVO + (g + 8) * 68 + mc];
            float m0 = acc[2] + biam.x, m1 = acc[3] + biam.y;
            float d0 = xv1.x - m0, d1 = xv1.y - m1;
            local += mt1 * 0.5f * (LOG_2PI + lv.x + d0 * d0 * expf(-lv.x));
            local += mt1 * 0.5f * (LOG_2PI + lv.y + d1 * d1 * expf(-lv.y));
        }
    }
    #pragma unroll
    for (int o = 16; o > 0; o >>= 1) local += __shfl_xor_sync(~0u, local, o);
    if (lane == 0) sh[RED + w] = local;
    __syncthreads();
    if (tid < 32) {
        float v = (tid < 16) ? sh[RED + tid] : 0.f;
        #pragma unroll
        for (int o = 8; o > 0; o >>= 1) v += __shfl_xor_sync(~0u, v, o);
        if (tid == 0) g_reconpart[t * 64 + gidx] = v;
    }
}

__global__ void __launch_bounds__(NTHR, 1)
scan_pairs(const float* __restrict__ bd2, const float* __restrict__ noise,
           const float* __restrict__ bp2, const float* __restrict__ X,
           float* __restrict__ out)
{
    extern __shared__ float sh[];
    unsigned* shu = (unsigned*)sh;
    const int role = blockIdx.x & 1;
    const int gidx = blockIdx.x >> 1;
    const int tid = threadIdx.x;
    const int w = tid >> 5, lane = tid & 31, g = lane >> 2, tig = lane & 3;
    const int r0 = gidx * 16;

    // resident W2 (once per kernel)
    load_w2r(shu, role ? g_Wp2T : g_Wd2T, tid);

    if (role == 0) {
        {   // init ZB (bf16) from z0
            int r = tid >> 5, c4 = (tid & 31) * 4;
            float4 z4 = ldcg4(&g_z[(size_t)(r0 + r) * ZDIM + c4]);
            shu[ZB + r * 68 + (c4 >> 1)]     = packbf(z4.x, z4.y);
            shu[ZB + r * 68 + (c4 >> 1) + 1] = packbf(z4.z, z4.w);
        }
        float zr[4];
        {
            int c = w * 8 + 2 * tig;
            float2 a = ldcg2(&g_z[(size_t)(r0 + g) * ZDIM + c]);
            float2 b = ldcg2(&g_z[(size_t)(r0 + g + 8) * ZDIM + c]);
            zr[0] = a.x; zr[1] = a.y; zr[2] = b.x; zr[3] = b.y;
        }
        __syncthreads();
        for (int t = 0; t < T_STEPS; t++)
            drift_step(t, bd2, noise, sh, zr, gidx, out);
    } else {
        __syncthreads();
        for (int t = 0; t < T_STEPS; t++)
            p_step(t, bp2, X, sh, gidx);
    }
}

// ---------------- outputs ---------------------------------------------------
__global__ void finalize(float* __restrict__ out, int out_size)
{
    int tid = threadIdx.x;   // 256
    if (tid < 64) { g_flag[tid] = 0; g_ack[tid] = 0; }   // reset for graph replay
    float k = 0.f, r = 0.f;
    for (int i = tid; i < T_STEPS * 64; i += 256) k += g_kldpart[i];
    for (int i = tid; i < T_STEPS * 64; i += 256) r += g_reconpart[i];
    __shared__ float rk[256], rr[256];
    rk[tid] = k; rr[tid] = r;
    __syncthreads();
    for (int s = 128; s > 0; s >>= 1) {
        if (tid < s) { rk[tid] += rk[tid + s]; rr[tid] += rr[tid + s]; }
        __syncthreads();
    }
    if (tid == 0) {
        float kld   = rk[0] * (0.5f * DT / (float)BS);
        float recon = rr[0] * (1.f / (float)BS);
        out[out_size - 3] = recon + kld;
        out[out_size - 2] = recon;
        out[out_size - 1] = kld;
    }
}

// ---------------- launch ----------------------------------------------------
extern "C" void kernel_launch(void* const* d_in, const int* in_sizes, int n_in,
                              void* d_out, int out_size)
{
    const float* X     = (const float*)d_in[0];
    const float* M     = (const float*)d_in[1];
    const float* cov   = (const float*)d_in[2];
    const float* ph    = (const float*)d_in[3];
    const float* phpos = (const float*)d_in[4];
    const float* noise = (const float*)d_in[5];
    const float* Wc1 = (const float*)d_in[6],  *bc1 = (const float*)d_in[7];
    const float* Wc2 = (const float*)d_in[8],  *bc2 = (const float*)d_in[9];
    const float* Wd1 = (const float*)d_in[10], *bd1 = (const float*)d_in[11];
    const float* Wd2 = (const float*)d_in[12], *bd2 = (const float*)d_in[13];
    const float* Wf1 = (const float*)d_in[14], *bf1 = (const float*)d_in[15];
    const float* Wf2 = (const float*)d_in[16], *bf2 = (const float*)d_in[17];
    const float* Wp1 = (const float*)d_in[18], *bp1 = (const float*)d_in[19];
    const float* Wp2 = (const float*)d_in[20], *bp2 = (const float*)d_in[21];
    float* out = (float*)d_out;

    static int smem_set = 0;
    if (!smem_set) {
        cudaFuncSetAttribute(scan_pairs,
                             cudaFuncAttributeMaxDynamicSharedMemorySize, SMEM_BYTES);
        smem_set = 1;
    }

    // ---- fused precompute: prep (z=4) overlapped with 4 h-GEMMs (z=0..3) ----
    gemm_pre5<<<dim3(4, 256, 5), 512>>>(ph, phpos, Wd1, bd1, Wp1, bp1, Wf1, bf1,
                                        cov, Wc1, bc1, Wc2, bc2, M, Wd2, Wp2);
    gemm_diff<<<dim3(1, 256), 512>>>(Wf2, bf2);

    // ---- bf16 pairwise scan (R13 core) ----
    scan_pairs<<<128, NTHR, SMEM_BYTES>>>(bd2, noise, bp2, X, out);

    // ---- losses + flag reset ----
    finalize<<<1, 256>>>(out, out_size);
}

// round 16
// speedup vs baseline: 1.0528x; 1.0055x over previous
#include <cuda_runtime.h>
#include <math.h>
#include <stdint.h>

#define T_STEPS 128
#define BATCH   128
#define SAMP    8
#define DIN     64
#define RDIM    256
#define ZDIM    128
#define HDIM    512
#define BS      1024
#define TB      16384
#define NTHR    512

#define DT       0.05f
#define SQRT_DT  0.22360679774997896f
#define LOG_2PI  1.8378770664093453f

// ---------------- scratch ---------------------------------------------------
__device__ __align__(16) float g_Hh[TB * HDIM];
__device__ __align__(16) float g_Hhpos[TB * HDIM];
__device__ __align__(16) float g_Hph[TB * HDIM];
__device__ __align__(16) float g_Hf[TB * HDIM];
__device__ __align__(16) float g_diff[TB * ZDIM];
__device__ __align__(16) float g_Mt[T_STEPS * BATCH];
__device__ __align__(16) float g_z[BS * ZDIM];
// bf16 transposed weights: WT[n][k/2] packed pairs (k even lo, k odd hi)
__device__ __align__(16) unsigned g_Wd1zT[HDIM * ZDIM / 2];  // [512][64]
__device__ __align__(16) unsigned g_Wd2T[ZDIM * HDIM / 2];   // [128][256]
__device__ __align__(16) unsigned g_Wp1zT[HDIM * ZDIM / 2];  // [512][64]
__device__ __align__(16) unsigned g_Wp2T[ZDIM * HDIM / 2];   // [128][256]
__device__ float g_kldpart[T_STEPS * 64];
__device__ float g_reconpart[T_STEPS * 64];
__device__ int g_flag[64];
__device__ int g_ack[64];

__device__ __forceinline__ float4 ldcg4(const float* p) { return __ldcg((const float4*)p); }
__device__ __forceinline__ float2 ldcg2(const float* p) { return __ldcg((const float2*)p); }
__device__ __forceinline__ unsigned f2tf(float f) {
    unsigned r; asm("cvt.rna.tf32.f32 %0, %1;" : "=r"(r) : "f"(f)); return r;
}
__device__ __forceinline__ unsigned packbf(float lo, float hi) {
    unsigned r; asm("cvt.rn.bf16x2.f32 %0, %1, %2;" : "=r"(r) : "f"(hi), "f"(lo)); return r;
}
#define FU(x)  __float_as_uint(x)
#define UF(x)  __uint_as_float(x)

__device__ __forceinline__ void mma8(float c[4], const unsigned a[4],
                                     unsigned b0, unsigned b1)
{
    asm volatile(
        "mma.sync.aligned.m16n8k8.row.col.f32.tf32.tf32.f32 "
        "{%0,%1,%2,%3}, {%4,%5,%6,%7}, {%8,%9}, {%0,%1,%2,%3};"
        : "+f"(c[0]), "+f"(c[1]), "+f"(c[2]), "+f"(c[3])
        : "r"(a[0]), "r"(a[1]), "r"(a[2]), "r"(a[3]), "r"(b0), "r"(b1));
}
__device__ __forceinline__ void mma16(float c[4], const unsigned a[4],
                                      unsigned b0, unsigned b1)
{
    asm volatile(
        "mma.sync.aligned.m16n8k16.row.col.f32.bf16.bf16.f32 "
        "{%0,%1,%2,%3}, {%4,%5,%6,%7}, {%8,%9}, {%0,%1,%2,%3};"
        : "+f"(c[0]), "+f"(c[1]), "+f"(c[2]), "+f"(c[3])
        : "r"(a[0]), "r"(a[1]), "r"(a[2]), "r"(a[3]), "r"(b0), "r"(b1));
}

// ---------------- tf32 MMA precompute GEMM body (ping-pong, reg prefetch) ---
// sA: 2 x [64][36], sB: 2 x [32][136]. One sync per 32-k chunk.
__device__ __forceinline__ void gemm_body(
    const float* __restrict__ A, const float* __restrict__ A2,
    const float* __restrict__ W, const float* __restrict__ bias,
    float* __restrict__ C, int M, int N, int K, int act,
    float* sA, float* sB)
{
    const int tid = threadIdx.x;
    const int w = tid >> 5, lane = tid & 31, g = lane >> 2, tig = lane & 3;
    const int bm = blockIdx.y * 64, bn = blockIdx.x * 128;
    const int mt = w & 3, n0 = (w >> 2) * 32;
    const int ar = tid >> 3, ac4 = (tid & 7) * 4;      // A staging slot (64x32)
    const int br0 = tid >> 5, bc0 = (tid & 31) * 4;    // B slot, first half
    const int br1 = (tid + 512) >> 5, bc1 = ((tid + 512) & 31) * 4;
    float acc[4][4] = {};
    float4 av, a2v, wva, wvb;

    // prologue: load chunk 0 + store to buffer 0
    av  = *(const float4*)&A[(size_t)(bm + ar) * K + ac4];
    if (A2) a2v = *(const float4*)&A2[(size_t)(bm + ar) * K + ac4];
    wva = *(const float4*)&W[(size_t)br0 * N + bn + bc0];
    wvb = *(const float4*)&W[(size_t)br1 * N + bn + bc1];
    {
        float x = av.x, y = av.y, z = av.z, u = av.w;
        if (A2) { x += a2v.x; y += a2v.y; z += a2v.z; u += a2v.w; }
        float* d = &sA[ar * 36 + ac4];
        d[0] = UF(f2tf(x)); d[1] = UF(f2tf(y)); d[2] = UF(f2tf(z)); d[3] = UF(f2tf(u));
        float* e0 = &sB[br0 * 136 + bc0];
        e0[0] = UF(f2tf(wva.x)); e0[1] = UF(f2tf(wva.y));
        e0[2] = UF(f2tf(wva.z)); e0[3] = UF(f2tf(wva.w));
        float* e1 = &sB[br1 * 136 + bc1];
        e1[0] = UF(f2tf(wvb.x)); e1[1] = UF(f2tf(wvb.y));
        e1[2] = UF(f2tf(wvb.z)); e1[3] = UF(f2tf(wvb.w));
    }

    const int NC = K >> 5;
    for (int c = 0; c < NC; c++) {
        __syncthreads();                       // buf c%2 published; buf (c+1)%2 free
        if (c + 1 < NC) {                      // prefetch next chunk to registers
            int k0 = (c + 1) * 32;
            av  = *(const float4*)&A[(size_t)(bm + ar) * K + k0 + ac4];
            if (A2) a2v = *(const float4*)&A2[(size_t)(bm + ar) * K + k0 + ac4];
            wva = *(const float4*)&W[(size_t)(k0 + br0) * N + bn + bc0];
            wvb = *(const float4*)&W[(size_t)(k0 + br1) * N + bn + bc1];
        }
        const float* pA = sA + (c & 1) * 2304 + (mt * 16 + g) * 36 + tig;
        const float* pB = sB + (c & 1) * 4352 + tig * 136 + n0 + g;
        #pragma unroll
        for (int kk = 0; kk < 4; kk++) {
            unsigned a[4] = { FU(pA[kk*8]), FU(pA[kk*8 + 288]),
                              FU(pA[kk*8 + 4]), FU(pA[kk*8 + 292]) };
            #pragma unroll
            for (int nt = 0; nt < 4; nt++) {
                unsigned b0 = FU(pB[kk*8*136 + nt*8]);
                unsigned b1 = FU(pB[(kk*8 + 4)*136 + nt*8]);
                mma8(acc[nt], a, b0, b1);
            }
        }
        if (c + 1 < NC) {                      // store prefetched chunk (loads landed)
            float* dA = sA + ((c + 1) & 1) * 2304;
            float* dB = sB + ((c + 1) & 1) * 4352;
            float x = av.x, y = av.y, z = av.z, u = av.w;
            if (A2) { x += a2v.x; y += a2v.y; z += a2v.z; u += a2v.w; }
            float* d = &dA[ar * 36 + ac4];
            d[0] = UF(f2tf(x)); d[1] = UF(f2tf(y)); d[2] = UF(f2tf(z)); d[3] = UF(f2tf(u));
            float* e0 = &dB[br0 * 136 + bc0];
            e0[0] = UF(f2tf(wva.x)); e0[1] = UF(f2tf(wva.y));
            e0[2] = UF(f2tf(wva.z)); e0[3] = UF(f2tf(wva.w));
            float* e1 = &dB[br1 * 136 + bc1];
            e1[0] = UF(f2tf(wvb.x)); e1[1] = UF(f2tf(wvb.y));
            e1[2] = UF(f2tf(wvb.z)); e1[3] = UF(f2tf(wvb.w));
        }
    }
    #pragma unroll
    for (int nt = 0; nt < 4; nt++) {
        int cb = bn + n0 + nt * 8 + 2 * tig;
        float b0 = bias[cb], b1 = bias[cb + 1];
        #pragma unroll
        for (int rh = 0; rh < 2; rh++) {
            int row = bm + mt * 16 + g + rh * 8;
            float v0 = acc[nt][rh*2] + b0, v1 = acc[nt][rh*2 + 1] + b1;
            if (act == 1) { v0 = fmaxf(v0, 0.f); v1 = fmaxf(v1, 0.f); }
            if (act == 2) { v0 = expf(v0); v1 = expf(v1); }
            *(float2*)&C[(size_t)row * N + cb] = make_float2(v0, v1);
        }
    }
}

// ---------------- prep body (z0 + Mt + transposes) --------------------------
__device__ void prep_body(int pid,
                          const float* __restrict__ cov,
                          const float* __restrict__ Wc1, const float* __restrict__ bc1,
                          const float* __restrict__ Wc2, const float* __restrict__ bc2,
                          const float* __restrict__ M,
                          const float* __restrict__ Wd1, const float* __restrict__ Wd2,
                          const float* __restrict__ Wp1, const float* __restrict__ Wp2,
                          float* sh)
{
    const int tid = threadIdx.x;   // 512, only tid<256 active for most
    if (pid < 128) {
        float* sc  = sh;        // [32]
        float* shh = sh + 32;   // [64]
        int b = pid;
        if (tid < 32) sc[tid] = cov[b * 32 + tid];
        __syncthreads();
        if (tid < 64) {
            float acc = bc1[tid];
            #pragma unroll
            for (int c = 0; c < 32; c++) acc = fmaf(sc[c], Wc1[c * 64 + tid], acc);
            shh[tid] = fmaxf(acc, 0.f);
        }
        __syncthreads();
        if (tid < 128) {
            float acc = bc2[tid];
            #pragma unroll
            for (int k = 0; k < 64; k++) acc = fmaf(shh[k], Wc2[k * 128 + tid], acc);
            float z = tanhf(acc);
            #pragma unroll
            for (int s = 0; s < SAMP; s++)
                g_z[(b * SAMP + s) * ZDIM + tid] = z;
        }
    } else if (pid < 160) {
        int i = (pid - 128) * 512 + tid;
        const float4* p = (const float4*)(M + (size_t)i * DIN);
        float s = 0.f;
        #pragma unroll
        for (int j = 0; j < DIN / 4; j++) { float4 v = p[j]; s += v.x + v.y + v.z + v.w; }
        g_Mt[i] = s * (1.f / (float)DIN);
    } else if (pid < 672) {
        int r = pid - 160;          // 0..511
        int which = r >> 7;
        int local = r & 127;
        const float* W; unsigned* WT; int K, N, bx, by;
        if (which == 0)      { W = Wd1 + RDIM * HDIM; WT = g_Wd1zT; K = ZDIM; N = HDIM;
                               bx = local & 15, by = local >> 4; }
        else if (which == 1) { W = Wd2;               WT = g_Wd2T;  K = HDIM; N = ZDIM;
                               bx = local & 3,  by = local >> 2; }
        else if (which == 2) { W = Wp1 + RDIM * HDIM; WT = g_Wp1zT; K = ZDIM; N = HDIM;
                               bx = local & 15, by = local >> 4; }
        else                 { W = Wp2;               WT = g_Wp2T;  K = HDIM; N = ZDIM;
                               bx = local & 3,  by = local >> 2; }
        if (tid < 256) {
            int n  = bx * 32 + (tid & 31);
            int kp = by * 8 + (tid >> 5);
            if (n < N && kp < K / 2) {
                float lo = W[(size_t)(2 * kp) * N + n];
                float hi = W[(size_t)(2 * kp + 1) * N + n];
                WT[(size_t)n * (K / 2) + kp] = packbf(lo, hi);
            }
        }
    }
}

// Fused 5-way: 4 h-projection GEMMs + prep (blockIdx.z == 4)
__global__ void __launch_bounds__(512, 2)
gemm_pre5(const float* __restrict__ ph, const float* __restrict__ phpos,
          const float* __restrict__ Wd1, const float* __restrict__ bd1,
          const float* __restrict__ Wp1, const float* __restrict__ bp1,
          const float* __restrict__ Wf1, const float* __restrict__ bf1,
          const float* __restrict__ cov,
          const float* __restrict__ Wc1, const float* __restrict__ bc1,
          const float* __restrict__ Wc2, const float* __restrict__ bc2,
          const float* __restrict__ M,
          const float* __restrict__ Wd2, const float* __restrict__ Wp2)
{
    __shared__ float sA[2 * 64 * 36];
    __shared__ float sB[2 * 32 * 136];
    const int which = blockIdx.z;
    if (which == 4) {
        int pid = blockIdx.y * 4 + blockIdx.x;   // 0..1023
        prep_body(pid, cov, Wc1, bc1, Wc2, bc2, M, Wd1, Wd2, Wp1, Wp2, sA);
        return;
    }
    const float* A2   = (which == 1) ? phpos : nullptr;
    const float* W    = (which <= 1) ? Wd1 : (which == 2 ? Wp1 : Wf1);
    const float* bias = (which <= 1) ? bd1 : (which == 2 ? bp1 : bf1);
    float* C = (which == 0) ? g_Hh : (which == 1 ? g_Hhpos : (which == 2 ? g_Hph : g_Hf));
    gemm_body(ph, A2, W, bias, C, TB, HDIM, RDIM, (which == 3) ? 1 : 0, sA, sB);
}

__global__ void __launch_bounds__(512, 2)
gemm_diff(const float* __restrict__ Wf2, const float* __restrict__ bf2)
{
    __shared__ float sA[2 * 64 * 36];
    __shared__ float sB[2 * 32 * 136];
    gemm_body(g_Hf, nullptr, Wf2, bf2, g_diff, TB, ZDIM, HDIM, 2, sA, sB);
}

// ================= bf16 pairwise scan (R13 core: streamed W1, resident W2) ==
// Block 2g: drift. Block 2g+1: p-head/NLL. 16 rows per pair, 1 block/SM.

// smem offsets (float/uint units) in DYNAMIC shared memory
#define ZB    0        /* z bf16 packed [16][68]        */
#define SAP   1088     /* A_p bf16 [16][68]             */
#define SAQ   2176     /* A_q bf16 [16][68] / LVO fp32  */
#define BB2   3264     /* stream dbl buf 2 x [128][36]  */
#define W2R   12480    /* resident W2 bf16 [128][260]   */
#define RED   45760    /* [32]                          */
#define SH_TOT 45792
#define SMEM_BYTES (SH_TOT * 4)
#define LVO   SAQ

__device__ __forceinline__ void pf_ld(const unsigned* base, int tid,
                                      uint4& b0, uint4& b1)
{
    b0 = *(const uint4*)(base + (size_t)(tid >> 3) * 64 + (tid & 7) * 4);
    b1 = *(const uint4*)(base + (size_t)((tid + 512) >> 3) * 64 + ((tid + 512) & 7) * 4);
}
__device__ __forceinline__ void pf_st(unsigned* buf, int tid, uint4 b0, uint4 b1)
{
    *(uint4*)&buf[(tid >> 3) * 36 + (tid & 7) * 4] = b0;
    *(uint4*)&buf[((tid + 512) >> 3) * 36 + ((tid + 512) & 7) * 4] = b1;
}

// preload z fragments (8 k16-groups x 4 regs) from ZB
__device__ __forceinline__ void load_za(const unsigned* shu, int g, int tig,
                                        unsigned za[8][4])
{
    const unsigned* pz = shu + ZB + g * 68 + tig;
    #pragma unroll
    for (int kk = 0; kk < 8; kk++) {
        za[kk][0] = pz[kk*8];
        za[kk][1] = pz[kk*8 + 544];
        za[kk][2] = pz[kk*8 + 4];
        za[kk][3] = pz[kk*8 + 548];
    }
}

// load resident W2 [128][256] -> smem [128][260]
__device__ __forceinline__ void load_w2r(unsigned* shu, const unsigned* W2T, int tid)
{
    #pragma unroll
    for (int i = 0; i < 16; i++) {
        int v = tid + i * 512;
        int r = v >> 6, c4 = (v & 63) * 4;
        *(uint4*)&shu[W2R + r * 260 + c4] = *(const uint4*)&W2T[(size_t)r * 256 + c4];
    }
}

__device__ void drift_step(int t, const float* __restrict__ bd2,
                           const float* __restrict__ noise,
                           float* sh, float zr[4], int gidx,
                           float* __restrict__ out)
{
    unsigned* shu = (unsigned*)sh;
    const int tid = threadIdx.x;
    const int w = tid >> 5, lane = tid & 31, g = lane >> 2, tig = lane & 3;
    const int r0 = gidx * 16;

    // ---- step-top prefetches (all in flight before any compute) ----
    uint4 br0, br1;
    pf_ld(g_Wd1zT, tid, br0, br1);                 // weight stage 0
    const int c = w * 8 + 2 * tig;
    const int cword = w * 4 + tig;
    const int bi0 = (r0 + g) >> 3,     si0 = (r0 + g) & 7;
    const int bi1 = (r0 + g + 8) >> 3, si1 = (r0 + g + 8) & 7;
    const size_t hb0 = (size_t)(t * BATCH + bi0) * HDIM;
    const size_t hb1 = (size_t)(t * BATCH + bi1) * HDIM;
    float2 hA0 = ldcg2(&g_Hh[hb0 + c]);
    float2 hA1 = ldcg2(&g_Hh[hb1 + c]);
    float2 hB0 = ldcg2(&g_Hhpos[hb0 + c]);
    float2 hB1 = ldcg2(&g_Hhpos[hb1 + c]);
    float2 dva = ldcg2(&g_diff[((size_t)t * BATCH + bi0) * ZDIM + c]);
    float2 dvb = ldcg2(&g_diff[((size_t)t * BATCH + bi1) * ZDIM + c]);
    float2 eva = ldcg2(&noise[(((size_t)t * BATCH + bi0) * SAMP + si0) * ZDIM + c]);
    float2 evb = ldcg2(&noise[(((size_t)t * BATCH + bi1) * SAMP + si1) * ZDIM + c]);
    float2 bia = *(const float2*)&bd2[c];

    unsigned za[8][4];
    load_za(shu, g, tig, za);

    float accp[4] = {0.f,0.f,0.f,0.f}, accq[4] = {0.f,0.f,0.f,0.f};

    for (int np = 0; np < 4; np++) {
        float ahz[4] = {0.f,0.f,0.f,0.f};
        #pragma unroll
        for (int st = 0; st < 2; st++) {
            int ss = np * 2 + st;
            unsigned* buf = shu + BB2 + (ss & 1) * 4608;
            pf_st(buf, tid, br0, br1);
            __syncthreads();
            if (ss < 7) {
                const unsigned* s = g_Wd1zT + (size_t)((ss + 1) >> 1) * 128 * 64
                                            + ((ss + 1) & 1) * 32;
                pf_ld(s, tid, br0, br1);
            }
            const unsigned* pB = buf + (w * 8 + g) * 36 + tig;
            #pragma unroll
            for (int kk = 0; kk < 4; kk++)
                mma16(ahz, za[st * 4 + kk], pB[kk*8], pB[kk*8 + 4]);
        }
        {   // intra-warp A construction: ahz fragment + h fragments -> SAP/SAQ
            shu[SAP + g * 68 + cword] =
                packbf(fmaxf(hA0.x + ahz[0], 0.f), fmaxf(hA0.y + ahz[1], 0.f));
            shu[SAP + (g + 8) * 68 + cword] =
                packbf(fmaxf(hA1.x + ahz[2], 0.f), fmaxf(hA1.y + ahz[3], 0.f));
            shu[SAQ + g * 68 + cword] =
                packbf(fmaxf(hB0.x + ahz[0], 0.f), fmaxf(hB0.y + ahz[1], 0.f));
            shu[SAQ + (g + 8) * 68 + cword] =
                packbf(fmaxf(hB1.x + ahz[2], 0.f), fmaxf(hB1.y + ahz[3], 0.f));
            if (np < 3) {   // prefetch next np h fragments
                int po = (np + 1) * 128 + c;
                hA0 = ldcg2(&g_Hh[hb0 + po]);
                hA1 = ldcg2(&g_Hh[hb1 + po]);
                hB0 = ldcg2(&g_Hhpos[hb0 + po]);
                hB1 = ldcg2(&g_Hhpos[hb1 + po]);
            }
        }
        __syncthreads();
        // drift dual MMA: resident W2R, NO syncs
        #pragma unroll
        for (int st2 = 0; st2 < 2; st2++) {
            const unsigned* pAp = shu + SAP + g * 68 + st2 * 32 + tig;
            const unsigned* pAq = shu + SAQ + g * 68 + st2 * 32 + tig;
            const unsigned* pB2 = shu + W2R + (w * 8 + g) * 260 + np * 64 + st2 * 32 + tig;
            #pragma unroll
            for (int kk = 0; kk < 4; kk++) {
                unsigned ap[4] = { pAp[kk*8], pAp[kk*8 + 544], pAp[kk*8 + 4], pAp[kk*8 + 548] };
                unsigned aq[4] = { pAq[kk*8], pAq[kk*8 + 544], pAq[kk*8 + 4], pAq[kk*8 + 548] };
                unsigned b0 = pB2[kk*8], b1 = pB2[kk*8 + 4];
                mma16(accp, ap, b0, b1);
                mma16(accq, aq, b0, b1);
            }
        }
    }

    // ---- epilogue: prior/poster, z update, KLD (operands prefetched) ----
    if (tid == 0) {
        while (((volatile int*)g_ack)[gidx] < t) __nanosleep(64);
    }
    __syncthreads();
    float kl = 0.f;
    {
        float pr0 = 0.1f * tanhf(accp[0] + bia.x);
        float pr1 = 0.1f * tanhf(accp[1] + bia.y);
        float po0 = 0.1f * tanhf(accq[0] + bia.x);
        float po1 = 0.1f * tanhf(accq[1] + bia.y);
        zr[0] += DT * po0 + SQRT_DT * dva.x * eva.x;
        zr[1] += DT * po1 + SQRT_DT * dva.y * eva.y;
        __stcg((float2*)&g_z[(size_t)(r0 + g) * ZDIM + c], make_float2(zr[0], zr[1]));
        if (t == T_STEPS - 1)
            *(float2*)&out[(size_t)(r0 + g) * ZDIM + c] = make_float2(zr[0], zr[1]);
        shu[ZB + g * 68 + (c >> 1)] = packbf(zr[0], zr[1]);
        float e0 = (pr0 - po0) / dva.x;
        float e1 = (pr1 - po1) / dva.y;
        kl += e0 * e0 + e1 * e1;
    }
    {
        float pr0 = 0.1f * tanhf(accp[2] + bia.x);
        float pr1 = 0.1f * tanhf(accp[3] + bia.y);
        float po0 = 0.1f * tanhf(accq[2] + bia.x);
        float po1 = 0.1f * tanhf(accq[3] + bia.y);
        zr[2] += DT * po0 + SQRT_DT * dvb.x * evb.x;
        zr[3] += DT * po1 + SQRT_DT * dvb.y * evb.y;
        __stcg((float2*)&g_z[(size_t)(r0 + g + 8) * ZDIM + c], make_float2(zr[2], zr[3]));
        if (t == T_STEPS - 1)
            *(float2*)&out[(size_t)(r0 + g + 8) * ZDIM + c] = make_float2(zr[2], zr[3]);
        shu[ZB + (g + 8) * 68 + (c >> 1)] = packbf(zr[2], zr[3]);
        float e0 = (pr0 - po0) / dvb.x;
        float e1 = (pr1 - po1) / dvb.y;
        kl += e0 * e0 + e1 * e1;
    }
    __threadfence();
    __syncthreads();
    if (tid == 0) ((volatile int*)g_flag)[gidx] = t + 1;
    #pragma unroll
    for (int o = 16; o > 0; o >>= 1) kl += __shfl_xor_sync(~0u, kl, o);
    if (lane == 0) sh[RED + w] = kl;
    __syncthreads();
    if (tid < 32) {
        float v = (tid < 16) ? sh[RED + tid] : 0.f;
        #pragma unroll
        for (int o = 8; o > 0; o >>= 1) v += __shfl_xor_sync(~0u, v, o);
        if (tid == 0) g_kldpart[t * 64 + gidx] = v;
    }
}

__device__ void p_step(int t, const float* __restrict__ bp2,
                       const float* __restrict__ X, float* sh, int gidx)
{
    unsigned* shu = (unsigned*)sh;
    const int tid = threadIdx.x;
    const int w = tid >> 5, lane = tid & 31, g = lane >> 2, tig = lane & 3;
    const int r0 = gidx * 16;

    // ---- step-top prefetches (independent of the z flag) ----
    uint4 br0, br1;
    pf_ld(g_Wp1zT, tid, br0, br1);
    const int c = w * 8 + 2 * tig;
    const int cword = w * 4 + tig;
    const int bi0 = (r0 + g) >> 3, bi1 = (r0 + g + 8) >> 3;
    const size_t hb0 = (size_t)(t * BATCH + bi0) * HDIM;
    const size_t hb1 = (size_t)(t * BATCH + bi1) * HDIM;
    float2 hP0 = ldcg2(&g_Hph[hb0 + c]);
    float2 hP1 = ldcg2(&g_Hph[hb1 + c]);
    float mt0 = g_Mt[t * BATCH + bi0];
    float mt1 = g_Mt[t * BATCH + bi1];
    float2 xv0 = make_float2(0.f, 0.f), xv1 = make_float2(0.f, 0.f);
    float2 biam = make_float2(0.f, 0.f), bial = make_float2(0.f, 0.f);
    if (w < 8) {
        int mc = w * 8 + 2 * tig;
        xv0 = *(const float2*)&X[((size_t)t * BATCH + bi0) * DIN + mc];
        xv1 = *(const float2*)&X[((size_t)t * BATCH + bi1) * DIN + mc];
        biam = *(const float2*)&bp2[mc];
    } else {
        bial = *(const float2*)&bp2[64 + (w - 8) * 8 + 2 * tig];
    }

    // wait for z(t+1), stage to ZB bf16
    if (tid == 0) {
        while (((volatile int*)g_flag)[gidx] < t + 1) __nanosleep(64);
        __threadfence();
    }
    __syncthreads();
    {
        int r = tid >> 5, c4 = (tid & 31) * 4;
        float4 z4 = ldcg4(&g_z[(size_t)(r0 + r) * ZDIM + c4]);
        shu[ZB + r * 68 + (c4 >> 1)]     = packbf(z4.x, z4.y);
        shu[ZB + r * 68 + (c4 >> 1) + 1] = packbf(z4.z, z4.w);
    }
    __syncthreads();
    if (tid == 0) {
        __threadfence();
        ((volatile int*)g_ack)[gidx] = t + 1;
    }

    unsigned za[8][4];
    load_za(shu, g, tig, za);

    float acc[4] = {0.f,0.f,0.f,0.f};
    for (int np = 0; np < 4; np++) {
        float ahz[4] = {0.f,0.f,0.f,0.f};
        #pragma unroll
        for (int st = 0; st < 2; st++) {
            int ss = np * 2 + st;
            unsigned* buf = shu + BB2 + (ss & 1) * 4608;
            pf_st(buf, tid, br0, br1);
            __syncthreads();
            if (ss < 7) {
                const unsigned* s = g_Wp1zT + (size_t)((ss + 1) >> 1) * 128 * 64
                                            + ((ss + 1) & 1) * 32;
                pf_ld(s, tid, br0, br1);
            }
            const unsigned* pB = buf + (w * 8 + g) * 36 + tig;
            #pragma unroll
            for (int kk = 0; kk < 4; kk++)
                mma16(ahz, za[st * 4 + kk], pB[kk*8], pB[kk*8 + 4]);
        }
        {   // intra-warp A construction
            shu[SAP + g * 68 + cword] =
                packbf(fmaxf(hP0.x + ahz[0], 0.f), fmaxf(hP0.y + ahz[1], 0.f));
            shu[SAP + (g + 8) * 68 + cword] =
                packbf(fmaxf(hP1.x + ahz[2], 0.f), fmaxf(hP1.y + ahz[3], 0.f));
            if (np < 3) {
                int po = (np + 1) * 128 + c;
                hP0 = ldcg2(&g_Hph[hb0 + po]);
                hP1 = ldcg2(&g_Hph[hb1 + po]);
            }
        }
        __syncthreads();
        #pragma unroll
        for (int st2 = 0; st2 < 2; st2++) {
            const unsigned* pAp = shu + SAP + g * 68 + st2 * 32 + tig;
            const unsigned* pB2 = shu + W2R + (w * 8 + g) * 260 + np * 64 + st2 * 32 + tig;
            #pragma unroll
            for (int kk = 0; kk < 4; kk++) {
                unsigned ap[4] = { pAp[kk*8], pAp[kk*8 + 544], pAp[kk*8 + 4], pAp[kk*8 + 548] };
                mma16(acc, ap, pB2[kk*8], pB2[kk*8 + 4]);
            }
        }
    }

    // ---- NLL epilogue (operands prefetched) ----
    __syncthreads();
    if (w >= 8) {   // logvar warps: export acc+bias (cols 64..127)
        int cb = (w - 8) * 8 + 2 * tig;
        *(float2*)&sh[LVO + g * 68 + cb]       = make_float2(acc[0] + bial.x, acc[1] + bial.y);
        *(float2*)&sh[LVO + (g + 8) * 68 + cb] = make_float2(acc[2] + bial.x, acc[3] + bial.y);
    }
    __syncthreads();
    float local = 0.f;
    if (w < 8) {
        int mc = w * 8 + 2 * tig;
        {
            float2 lv = *(float2*)&sh[LVO + g * 68 + mc];
            float m0 = acc[0] + biam.x, m1 = acc[1] + biam.y;
            float d0 = xv0.x - m0, d1 = xv0.y - m1;
            local += mt0 * 0.5f * (LOG_2PI + lv.x + d0 * d0 * expf(-lv.x));
            local += mt0 * 0.5f * (LOG_2PI + lv.y + d1 * d1 * expf(-lv.y));
        }
        {
            float2 lv = *(float2*)&sh[LVO + (g + 8) * 68 + mc];
            float m0 = acc[2] + biam.x, m1 = acc[3] + biam.y;
            float d0 = xv1.x - m0, d1 = xv1.y - m1;
            local += mt1 * 0.5f * (LOG_2PI + lv.x + d0 * d0 * expf(-lv.x));
            local += mt1 * 0.5f * (LOG_2PI + lv.y + d1 * d1 * expf(-lv.y));
        }
    }
    #pragma unroll
    for (int o = 16; o > 0; o >>= 1) local += __shfl_xor_sync(~0u, local, o);
    if (lane == 0) sh[RED + w] = local;
    __syncthreads();
    if (tid < 32) {
        float v = (tid < 16) ? sh[RED + tid] : 0.f;
        #pragma unroll
        for (int o = 8; o > 0; o >>= 1) v += __shfl_xor_sync(~0u, v, o);
        if (tid == 0) g_reconpart[t * 64 + gidx] = v;
    }
}

__global__ void __launch_bounds__(NTHR, 1)
scan_pairs(const float* __restrict__ bd2, const float* __restrict__ noise,
           const float* __restrict__ bp2, const float* __restrict__ X,
           float* __restrict__ out)
{
    extern __shared__ float sh[];
    unsigned* shu = (unsigned*)sh;
    const int role = blockIdx.x & 1;
    const int gidx = blockIdx.x >> 1;
    const int tid = threadIdx.x;
    const int w = tid >> 5, lane = tid & 31, g = lane >> 2, tig = lane & 3;
    const int r0 = gidx * 16;

    // resident W2 (once per kernel)
    load_w2r(shu, role ? g_Wp2T : g_Wd2T, tid);

    if (role == 0) {
        {   // init ZB (bf16) from z0
            int r = tid >> 5, c4 = (tid & 31) * 4;
            float4 z4 = ldcg4(&g_z[(size_t)(r0 + r) * ZDIM + c4]);
            shu[ZB + r * 68 + (c4 >> 1)]     = packbf(z4.x, z4.y);
            shu[ZB + r * 68 + (c4 >> 1) + 1] = packbf(z4.z, z4.w);
        }
        float zr[4];
        {
            int c = w * 8 + 2 * tig;
            float2 a = ldcg2(&g_z[(size_t)(r0 + g) * ZDIM + c]);
            float2 b = ldcg2(&g_z[(size_t)(r0 + g + 8) * ZDIM + c]);
            zr[0] = a.x; zr[1] = a.y; zr[2] = b.x; zr[3] = b.y;
        }
        __syncthreads();
        for (int t = 0; t < T_STEPS; t++)
            drift_step(t, bd2, noise, sh, zr, gidx, out);
    } else {
        __syncthreads();
        for (int t = 0; t < T_STEPS; t++)
            p_step(t, bp2, X, sh, gidx);
    }
}

// ---------------- outputs ---------------------------------------------------
__global__ void finalize(float* __restrict__ out, int out_size)
{
    int tid = threadIdx.x;   // 256
    if (tid < 64) { g_flag[tid] = 0; g_ack[tid] = 0; }   // reset for graph replay
    float k = 0.f, r = 0.f;
    for (int i = tid; i < T_STEPS * 64; i += 256) k += g_kldpart[i];
    for (int i = tid; i < T_STEPS * 64; i += 256) r += g_reconpart[i];
    __shared__ float rk[256], rr[256];
    rk[tid] = k; rr[tid] = r;
    __syncthreads();
    for (int s = 128; s > 0; s >>= 1) {
        if (tid < s) { rk[tid] += rk[tid + s]; rr[tid] += rr[tid + s]; }
        __syncthreads();
    }
    if (tid == 0) {
        float kld   = rk[0] * (0.5f * DT / (float)BS);
        float recon = rr[0] * (1.f / (float)BS);
        out[out_size - 3] = recon + kld;
        out[out_size - 2] = recon;
        out[out_size - 1] = kld;
    }
}

// ---------------- launch ----------------------------------------------------
extern "C" void kernel_launch(void* const* d_in, const int* in_sizes, int n_in,
                              void* d_out, int out_size)
{
    const float* X     = (const float*)d_in[0];
    const float* M     = (const float*)d_in[1];
    const float* cov   = (const float*)d_in[2];
    const float* ph    = (const float*)d_in[3];
    const float* phpos = (const float*)d_in[4];
    const float* noise = (const float*)d_in[5];
    const float* Wc1 = (const float*)d_in[6],  *bc1 = (const float*)d_in[7];
    const float* Wc2 = (const float*)d_in[8],  *bc2 = (const float*)d_in[9];
    const float* Wd1 = (const float*)d_in[10], *bd1 = (const float*)d_in[11];
    const float* Wd2 = (const float*)d_in[12], *bd2 = (const float*)d_in[13];
    const float* Wf1 = (const float*)d_in[14], *bf1 = (const float*)d_in[15];
    const float* Wf2 = (const float*)d_in[16], *bf2 = (const float*)d_in[17];
    const float* Wp1 = (const float*)d_in[18], *bp1 = (const float*)d_in[19];
    const float* Wp2 = (const float*)d_in[20], *bp2 = (const float*)d_in[21];
    float* out = (float*)d_out;

    static int smem_set = 0;
    if (!smem_set) {
        cudaFuncSetAttribute(scan_pairs,
                             cudaFuncAttributeMaxDynamicSharedMemorySize, SMEM_BYTES);
        smem_set = 1;
    }

    // ---- fused precompute: prep (z=4) overlapped with 4 h-GEMMs (z=0..3) ----
    gemm_pre5<<<dim3(4, 256, 5), 512>>>(ph, phpos, Wd1, bd1, Wp1, bp1, Wf1, bf1,
                                        cov, Wc1, bc1, Wc2, bc2, M, Wd2, Wp2);
    gemm_diff<<<dim3(1, 256), 512>>>(Wf2, bf2);

    // ---- bf16 pairwise scan (R13 core) ----
    scan_pairs<<<128, NTHR, SMEM_BYTES>>>(bd2, noise, bp2, X, out);

    // ---- losses + flag reset ----
    finalize<<<1, 256>>>(out, out_size);
}